// round 1
// baseline (speedup 1.0000x reference)
#include <cuda_runtime.h>
#include <math.h>

#define S_LEN  2048
#define BSZ    2
#define DMODEL 512
#define NHEADS 8
#define DHEAD  64
#define ZB     (BSZ*NHEADS)          // 16
#define MROWS  (S_LEN*BSZ)           // 4096
#define NWIN   32                    // windows in second dilation pass

// Scratch (static device allocation — no cudaMalloc allowed)
__device__ float g_Q[ZB*S_LEN*DHEAD];     // scaled q, [z][s][d]
__device__ float g_K[ZB*S_LEN*DHEAD];
__device__ float g_V[ZB*S_LEN*DHEAD];
__device__ float g_k2[ZB*DHEAD];
__device__ float g_v2[ZB*DHEAD];
__device__ float g_rows[BSZ*NWIN*DMODEL]; // pre-projection rows [batch][win][dm]

// ---------------------------------------------------------------------------
// Kernel 1: fused QKV projection.
// C[m,n] = sum_k x[m,k] * W[nn,k]  (NT gemm), m in [0,4096), n in [0,1536)
// Stores into g_Q/g_K/g_V in [z][s][d] layout; q gets 1/(8*exp(beta[h])) scale.
// Tile 128x128x8, 256 threads, 8x8 per thread with split-tile mapping.
// ---------------------------------------------------------------------------
__global__ __launch_bounds__(256) void gemm_qkv(
    const float* __restrict__ x,
    const float* __restrict__ Wq, const float* __restrict__ bq,
    const float* __restrict__ Wk, const float* __restrict__ bk,
    const float* __restrict__ Wv, const float* __restrict__ bv,
    const float* __restrict__ beta)
{
    const int bn = blockIdx.x;           // 0..11
    const int bm = blockIdx.y;           // 0..31
    const int nglob0 = bn * 128;
    const int sel   = nglob0 / DMODEL;   // 0=Q,1=K,2=V (128 | 512, so constant per block)
    const int nbase = nglob0 % DMODEL;   // 0,128,256,384

    const float* __restrict__ W   = (sel==0) ? Wq : (sel==1) ? Wk : Wv;
    const float* __restrict__ bia = (sel==0) ? bq : (sel==1) ? bk : bv;
    float* __restrict__ dst       = (sel==0) ? g_Q : (sel==1) ? g_K : g_V;

    __shared__ __align__(16) float As[8][128];
    __shared__ __align__(16) float Bs[8][128];

    const int tid = threadIdx.x;
    const int tx  = tid & 15;            // n sub-tile
    const int ty  = tid >> 4;            // m sub-tile

    const int lrow = tid >> 1;           // 0..127 : row loaded by this thread
    const int lk   = (tid & 1) * 4;      // 0 or 4 : k offset (float4)

    const float* Ap = x + (size_t)(bm*128 + lrow)*DMODEL + lk;
    const float* Bp = W + (size_t)(nbase + lrow)*DMODEL + lk;

    float acc[8][8];
    #pragma unroll
    for (int i=0;i<8;i++)
        #pragma unroll
        for (int j=0;j<8;j++) acc[i][j]=0.f;

    for (int k0=0; k0<DMODEL; k0+=8) {
        float4 a = *(const float4*)(Ap + k0);
        float4 b = *(const float4*)(Bp + k0);
        As[lk+0][lrow]=a.x; As[lk+1][lrow]=a.y; As[lk+2][lrow]=a.z; As[lk+3][lrow]=a.w;
        Bs[lk+0][lrow]=b.x; Bs[lk+1][lrow]=b.y; Bs[lk+2][lrow]=b.z; Bs[lk+3][lrow]=b.w;
        __syncthreads();
        #pragma unroll
        for (int k=0;k<8;k++) {
            float4 a0 = *(const float4*)&As[k][ty*4];
            float4 a1 = *(const float4*)&As[k][64+ty*4];
            float4 b0 = *(const float4*)&Bs[k][tx*4];
            float4 b1 = *(const float4*)&Bs[k][64+tx*4];
            float ar[8] = {a0.x,a0.y,a0.z,a0.w,a1.x,a1.y,a1.z,a1.w};
            float br[8] = {b0.x,b0.y,b0.z,b0.w,b1.x,b1.y,b1.z,b1.w};
            #pragma unroll
            for (int i=0;i<8;i++)
                #pragma unroll
                for (int j=0;j<8;j++)
                    acc[i][j] = fmaf(ar[i], br[j], acc[i][j]);
        }
        __syncthreads();
    }

    // Epilogue: bias, optional q-scale, scatter to [z][s][d] (float4 stores).
    #pragma unroll
    for (int g=0; g<2; g++) {
        const int col  = g*64 + tx*4;        // column within 128-wide tile
        const int nn   = nbase + col;        // column within matrix
        const int head = nn >> 6;
        const int dcol = tx*4;               // nn & 63 == tx*4 (nbase % 64 == 0)
        float scale = 1.0f;
        if (sel == 0) scale = 1.0f / (8.0f * expf(beta[head]));
        float4 bv4 = *(const float4*)(bia + nn);
        #pragma unroll
        for (int i=0;i<8;i++) {
            int mloc = (i<4) ? (ty*4+i) : (64 + ty*4 + (i-4));
            int m = bm*128 + mloc;
            int s_idx = m >> 1;
            int b_idx = m & 1;
            int z = b_idx*NHEADS + head;
            float4 o;
            o.x = (acc[i][g*4+0] + bv4.x) * scale;
            o.y = (acc[i][g*4+1] + bv4.y) * scale;
            o.z = (acc[i][g*4+2] + bv4.z) * scale;
            o.w = (acc[i][g*4+3] + bv4.w) * scale;
            *(float4*)&dst[((size_t)z*S_LEN + s_idx)*DHEAD + dcol] = o;
        }
    }
}

// ---------------------------------------------------------------------------
// Kernel 2: per-z reduction (dilation pass 0).
// w(s) = sigmoid(qhat[z,s]·k[z,s]);  k2[z] = sum_s w*k,  v2[z] = sum_s w*v.
// One block per z (16 blocks), 8 warps; each warp strides over s, each lane
// owns 2 of the 64 d-components.
// ---------------------------------------------------------------------------
__global__ __launch_bounds__(256) void reduce_kv()
{
    const int z    = blockIdx.x;
    const int warp = threadIdx.x >> 5;
    const int lane = threadIdx.x & 31;

    const float* __restrict__ Q = g_Q + (size_t)z*S_LEN*DHEAD;
    const float* __restrict__ K = g_K + (size_t)z*S_LEN*DHEAD;
    const float* __restrict__ V = g_V + (size_t)z*S_LEN*DHEAD;

    float k2a=0.f, k2b=0.f, v2a=0.f, v2b=0.f;

    for (int s = warp; s < S_LEN; s += 8) {
        const float2 qv = *(const float2*)(Q + (size_t)s*DHEAD + lane*2);
        const float2 kv = *(const float2*)(K + (size_t)s*DHEAD + lane*2);
        const float2 vv = *(const float2*)(V + (size_t)s*DHEAD + lane*2);
        float part = qv.x*kv.x + qv.y*kv.y;
        #pragma unroll
        for (int off=16; off; off>>=1)
            part += __shfl_xor_sync(0xFFFFFFFFu, part, off);
        const float w = 1.0f / (1.0f + expf(-part));   // softmax([p,0])[0]
        k2a = fmaf(w, kv.x, k2a);  k2b = fmaf(w, kv.y, k2b);
        v2a = fmaf(w, vv.x, v2a);  v2b = fmaf(w, vv.y, v2b);
    }

    __shared__ float sk[8][64];
    __shared__ float sv[8][64];
    sk[warp][lane*2] = k2a;  sk[warp][lane*2+1] = k2b;
    sv[warp][lane*2] = v2a;  sv[warp][lane*2+1] = v2b;
    __syncthreads();
    if (threadIdx.x < 64) {
        float a=0.f, b=0.f;
        #pragma unroll
        for (int w=0; w<8; w++) { a += sk[w][threadIdx.x]; b += sv[w][threadIdx.x]; }
        g_k2[z*DHEAD + threadIdx.x] = a;
        g_v2[z*DHEAD + threadIdx.x] = b;
    }
}

// ---------------------------------------------------------------------------
// Kernel 3: dilation pass 1 at s=2047 (the only live position).
// scores s_b = qhat[z, 64b+63]·k2[z]; softmax with sink; coefficient c_b
// (c_31 += 1 from pass-0 contribution). rows[batch][b][head*64+d] = c_b*v2[z,d].
// One block, 16 warps (warp = z, lane = window index b).
// ---------------------------------------------------------------------------
__global__ __launch_bounds__(512) void window_kernel()
{
    const int z    = threadIdx.x >> 5;   // 0..15
    const int lane = threadIdx.x & 31;   // window b 0..31

    const float* __restrict__ q  = g_Q + ((size_t)z*S_LEN + (64*lane + 63))*DHEAD;
    const float* __restrict__ k2 = g_k2 + z*DHEAD;

    float s = 0.f;
    #pragma unroll
    for (int d=0; d<DHEAD; d++) s = fmaf(q[d], k2[d], s);

    float mx = s;
    #pragma unroll
    for (int off=16; off; off>>=1)
        mx = fmaxf(mx, __shfl_xor_sync(0xFFFFFFFFu, mx, off));
    mx = fmaxf(mx, 0.f);                         // sink score 0
    const float e = expf(s - mx);
    float sum = e;
    #pragma unroll
    for (int off=16; off; off>>=1)
        sum += __shfl_xor_sync(0xFFFFFFFFu, sum, off);
    sum += expf(-mx);                            // sink term
    float c = e / sum;
    if (lane == 31) c += 1.0f;                   // pass-0 v2 at position 2047

    const int b_idx = z >> 3;
    const int head  = z & 7;
    const float* __restrict__ v2 = g_v2 + z*DHEAD;
    float* __restrict__ row = g_rows + ((size_t)(b_idx*NWIN + lane))*DMODEL + head*DHEAD;
    #pragma unroll
    for (int d=0; d<DHEAD; d++) row[d] = c * v2[d];
}

// ---------------------------------------------------------------------------
// Kernel 4: fill entire output with bo (positions < 2016 keep it; the last 32
// rows are overwritten by proj_out which runs after in-stream).
// ---------------------------------------------------------------------------
__global__ void fill_out(float* __restrict__ out, const float* __restrict__ bo)
{
    int idx = blockIdx.x*blockDim.x + threadIdx.x;
    if (idx < S_LEN*BSZ*DMODEL) out[idx] = bo[idx & (DMODEL-1)];
}

// ---------------------------------------------------------------------------
// Kernel 5: output projection of the 64 live rows: out = row @ Wo^T + bo.
// One block per (window, batch) row; 512 threads = one output column each.
// ---------------------------------------------------------------------------
__global__ __launch_bounds__(512) void proj_out(
    float* __restrict__ out,
    const float* __restrict__ Wo,
    const float* __restrict__ bo)
{
    const int wb    = blockIdx.x >> 1;
    const int batch = blockIdx.x & 1;

    __shared__ __align__(16) float in[DMODEL];
    for (int i = threadIdx.x; i < DMODEL; i += blockDim.x)
        in[i] = g_rows[((size_t)(batch*NWIN + wb))*DMODEL + i];
    __syncthreads();

    const int n = threadIdx.x;
    const float4* __restrict__ w = (const float4*)(Wo + (size_t)n*DMODEL);
    float acc = 0.f;
    #pragma unroll 4
    for (int k4 = 0; k4 < DMODEL/4; k4++) {
        float4 wv = w[k4];
        const float4 iv = *(const float4*)&in[k4*4];
        acc = fmaf(iv.x, wv.x, acc);
        acc = fmaf(iv.y, wv.y, acc);
        acc = fmaf(iv.z, wv.z, acc);
        acc = fmaf(iv.w, wv.w, acc);
    }
    out[((size_t)((2016 + wb)*BSZ + batch))*DMODEL + n] = acc + bo[n];
}

// ---------------------------------------------------------------------------
extern "C" void kernel_launch(void* const* d_in, const int* in_sizes, int n_in,
                              void* d_out, int out_size)
{
    const float* x    = (const float*)d_in[0];
    const float* Wq   = (const float*)d_in[1];
    const float* bq   = (const float*)d_in[2];
    const float* Wk   = (const float*)d_in[3];
    const float* bk   = (const float*)d_in[4];
    const float* Wv   = (const float*)d_in[5];
    const float* bv   = (const float*)d_in[6];
    const float* Wo   = (const float*)d_in[7];
    const float* bo   = (const float*)d_in[8];
    const float* beta = (const float*)d_in[9];
    float* out = (float*)d_out;

    dim3 g1(12, 32);
    gemm_qkv<<<g1, 256>>>(x, Wq, bq, Wk, bk, Wv, bv, beta);
    reduce_kv<<<ZB, 256>>>();
    window_kernel<<<1, 512>>>();
    fill_out<<<(S_LEN*BSZ*DMODEL + 255)/256, 256>>>(out, bo);
    proj_out<<<2*NWIN, 512>>>(out, Wo, bo);
}

// round 3
// speedup vs baseline: 2.2476x; 2.2476x over previous
#include <cuda_runtime.h>
#include <cuda_bf16.h>
#include <math.h>
#include <stdint.h>

#define S_LEN  2048
#define BSZ    2
#define DMODEL 512
#define NHEADS 8
#define DHEAD  64
#define ZB     (BSZ*NHEADS)          // 16
#define MROWS  (S_LEN*BSZ)           // 4096
#define NWIN   32
#define KTOT   1536                  // 3x512 (hi | lo | hi)
#define NTOT   1536                  // Q,K,V columns stacked
#define KC     64                    // K chunk (bf16) = 128B rows
#define NCHUNK (KTOT/KC)             // 24
#define STAGES 3
#define ATILE  16384                 // 128 x 64 bf16
#define BTILE  16384
#define STAGE_BYTES (ATILE+BTILE)
#define SMEM_BYTES  (STAGES*STAGE_BYTES)   // 96 KB

// ---------------- static scratch (no cudaMalloc allowed) -------------------
__device__ __align__(16) __nv_bfloat16 g_Xc[(size_t)MROWS*KTOT]; // 12.6 MB
__device__ __align__(16) __nv_bfloat16 g_Wc[(size_t)NTOT*KTOT];  //  4.7 MB
__device__ float g_Q[(size_t)ZB*S_LEN*DHEAD];
__device__ float g_K[(size_t)ZB*S_LEN*DHEAD];
__device__ float g_V[(size_t)ZB*S_LEN*DHEAD];
__device__ float g_k2p[ZB*8*DHEAD];
__device__ float g_v2p[ZB*8*DHEAD];
__device__ float g_rows[BSZ*NWIN*DMODEL];

// ---------------- helpers ---------------------------------------------------
__device__ __forceinline__ uint32_t smem_u32(const void* p) {
    uint32_t a;
    asm("{ .reg .u64 t; cvta.to.shared.u64 t, %1; cvt.u32.u64 %0, t; }"
        : "=r"(a) : "l"(p));
    return a;
}
__device__ __forceinline__ uint32_t swz(uint32_t off) {
    return off ^ ((off >> 3) & 0x70);      // SW128: flip bits[6:4] by bits[9:7]
}
__device__ __forceinline__ void cp16(uint32_t saddr, const void* g) {
    asm volatile("cp.async.cg.shared.global [%0], [%1], 16;"
                 :: "r"(saddr), "l"(g) : "memory");
}
#define CP_COMMIT() asm volatile("cp.async.commit_group;" ::: "memory")
#define CP_WAIT(n)  asm volatile("cp.async.wait_group %0;" :: "n"(n) : "memory")

__device__ __forceinline__ void ldmx4(uint32_t& r0, uint32_t& r1,
                                      uint32_t& r2, uint32_t& r3, uint32_t a) {
    asm volatile("ldmatrix.sync.aligned.m8n8.x4.shared.b16 {%0,%1,%2,%3}, [%4];"
                 : "=r"(r0), "=r"(r1), "=r"(r2), "=r"(r3) : "r"(a));
}
__device__ __forceinline__ void mma16816(float* c, const uint32_t* a,
                                         uint32_t b0, uint32_t b1) {
    asm volatile(
        "mma.sync.aligned.m16n8k16.row.col.f32.bf16.bf16.f32 "
        "{%0,%1,%2,%3}, {%4,%5,%6,%7}, {%8,%9}, {%0,%1,%2,%3};"
        : "+f"(c[0]), "+f"(c[1]), "+f"(c[2]), "+f"(c[3])
        : "r"(a[0]), "r"(a[1]), "r"(a[2]), "r"(a[3]), "r"(b0), "r"(b1));
}

// ---------------------------------------------------------------------------
// Kernel A: x -> bf16 hi/lo split layout. Xc[m] = [hi(512) | lo(512) | hi(512)]
// ---------------------------------------------------------------------------
__global__ __launch_bounds__(256) void convert_x(const float* __restrict__ x)
{
    int idx = blockIdx.x * 256 + threadIdx.x;
    if (idx >= MROWS * DMODEL) return;
    int m = idx >> 9, k = idx & 511;
    float v = x[idx];
    __nv_bfloat16 hi = __float2bfloat16(v);
    __nv_bfloat16 lo = __float2bfloat16(v - __bfloat162float(hi));
    size_t base = (size_t)m * KTOT;
    g_Xc[base + k]        = hi;
    g_Xc[base + 512 + k]  = lo;
    g_Xc[base + 1024 + k] = hi;
}

// Kernel B: Wq/Wk/Wv -> Wc[n] = [hi | hi | lo]
__global__ __launch_bounds__(256) void convert_w(
    const float* __restrict__ Wq, const float* __restrict__ Wk,
    const float* __restrict__ Wv)
{
    int idx = blockIdx.x * 256 + threadIdx.x;
    if (idx >= NTOT * DMODEL) return;
    int n = idx >> 9, k = idx & 511;
    int sel = n >> 9, row = n & 511;
    const float* W = (sel == 0) ? Wq : (sel == 1) ? Wk : Wv;
    float v = W[(size_t)row * DMODEL + k];
    __nv_bfloat16 hi = __float2bfloat16(v);
    __nv_bfloat16 lo = __float2bfloat16(v - __bfloat162float(hi));
    size_t base = (size_t)n * KTOT;
    g_Wc[base + k]        = hi;
    g_Wc[base + 512 + k]  = hi;
    g_Wc[base + 1024 + k] = lo;
}

// ---------------------------------------------------------------------------
// Kernel C: bf16 warp-MMA GEMM  C[4096,1536] = Xc @ Wc^T  (K=1536)
// 128x128 tile/CTA, 8 warps (4m x 2n), warp tile 32x64, mma.m16n8k16.
// 3-stage cp.async pipeline, SW128-swizzled smem, ldmatrix fragments.
// Epilogue: bias + q-scale + scatter to g_Q/g_K/g_V [z][s][d] fp32.
// ---------------------------------------------------------------------------
__global__ __launch_bounds__(256, 2) void gemm_mma(
    const float* __restrict__ bq, const float* __restrict__ bk,
    const float* __restrict__ bv, const float* __restrict__ beta)
{
    extern __shared__ __align__(1024) char smem[];
    const uint32_t sbase = smem_u32(smem);
    const int tid  = threadIdx.x;
    const int lane = tid & 31;
    const int wid  = tid >> 5;
    const int bn = blockIdx.x;           // 0..11
    const int bm = blockIdx.y;           // 0..31

    const __nv_bfloat16* __restrict__ Xb = g_Xc + (size_t)(bm * 128) * KTOT;
    const __nv_bfloat16* __restrict__ Wb = g_Wc + (size_t)(bn * 128) * KTOT;

    // -- cp.async slots: each thread copies 4 rows x 16B for A and B --------
    const int r0  = tid >> 3;            // 0..31
    const int c16 = tid & 7;             // 16B column within 128B row
    uint32_t so[4];
    #pragma unroll
    for (int j = 0; j < 4; j++)
        so[j] = swz((uint32_t)((r0 + 32 * j) * 128 + c16 * 16));

    // -- warp/fragment geometry ---------------------------------------------
    const int wm = wid & 3;              // m warp 0..3 (32 rows each)
    const int wn = wid >> 2;             // n warp 0..1 (64 cols each)
    const int g  = lane >> 2;            // group id 0..7
    const int t  = lane & 3;             // thread-in-group

    // ldmatrix lane addresses (byte offsets within tile, pre-swizzle)
    const int a_row = wm * 32 + (lane & 15);            // + mt*16
    const int a_kb  = (lane >> 4) * 16;                 // + k16*32
    const int b_row = wn * 64 + (lane & 7) + (lane >> 4) * 8;  // + nt2*16
    const int b_kb  = ((lane >> 3) & 1) * 16;           // + k16*32

    float acc[2][8][4];
    #pragma unroll
    for (int i = 0; i < 2; i++)
        #pragma unroll
        for (int j = 0; j < 8; j++)
            #pragma unroll
            for (int q = 0; q < 4; q++) acc[i][j][q] = 0.f;

    // -- pipeline ------------------------------------------------------------
    #pragma unroll
    for (int s = 0; s < STAGES - 1; s++) {
        uint32_t sA = sbase + s * STAGE_BYTES;
        uint32_t sB = sA + ATILE;
        const __nv_bfloat16* gA = Xb + (size_t)s * KC + c16 * 8;
        const __nv_bfloat16* gB = Wb + (size_t)s * KC + c16 * 8;
        #pragma unroll
        for (int j = 0; j < 4; j++) {
            cp16(sA + so[j], gA + (size_t)(r0 + 32 * j) * KTOT);
            cp16(sB + so[j], gB + (size_t)(r0 + 32 * j) * KTOT);
        }
        CP_COMMIT();
    }

    for (int i = 0; i < NCHUNK; i++) {
        CP_WAIT(STAGES - 2);
        __syncthreads();

        const int nxt = i + STAGES - 1;
        if (nxt < NCHUNK) {
            const int st = nxt % STAGES;
            uint32_t sA = sbase + st * STAGE_BYTES;
            uint32_t sB = sA + ATILE;
            const __nv_bfloat16* gA = Xb + (size_t)nxt * KC + c16 * 8;
            const __nv_bfloat16* gB = Wb + (size_t)nxt * KC + c16 * 8;
            #pragma unroll
            for (int j = 0; j < 4; j++) {
                cp16(sA + so[j], gA + (size_t)(r0 + 32 * j) * KTOT);
                cp16(sB + so[j], gB + (size_t)(r0 + 32 * j) * KTOT);
            }
        }
        CP_COMMIT();

        // compute chunk i from stage i%STAGES
        const uint32_t sA = sbase + (i % STAGES) * STAGE_BYTES;
        const uint32_t sB = sA + ATILE;
        #pragma unroll
        for (int k16 = 0; k16 < 4; k16++) {
            uint32_t af[2][4];
            #pragma unroll
            for (int mt = 0; mt < 2; mt++) {
                uint32_t addr = sA + swz((uint32_t)((a_row + mt * 16) * 128
                                                    + k16 * 32 + a_kb));
                ldmx4(af[mt][0], af[mt][1], af[mt][2], af[mt][3], addr);
            }
            uint32_t bf[8][2];
            #pragma unroll
            for (int nt2 = 0; nt2 < 4; nt2++) {
                uint32_t addr = sB + swz((uint32_t)((b_row + nt2 * 16) * 128
                                                    + k16 * 32 + b_kb));
                uint32_t q0, q1, q2, q3;
                ldmx4(q0, q1, q2, q3, addr);
                bf[nt2 * 2 + 0][0] = q0; bf[nt2 * 2 + 0][1] = q1;
                bf[nt2 * 2 + 1][0] = q2; bf[nt2 * 2 + 1][1] = q3;
            }
            #pragma unroll
            for (int mt = 0; mt < 2; mt++)
                #pragma unroll
                for (int nt = 0; nt < 8; nt++)
                    mma16816(acc[mt][nt], af[mt], bf[nt][0], bf[nt][1]);
        }
    }

    // -- epilogue -------------------------------------------------------------
    const int sel   = bn >> 2;                 // 0=Q,1=K,2=V
    const int nbase = (bn & 3) * 128;
    const float* __restrict__ bia = (sel == 0) ? bq : (sel == 1) ? bk : bv;
    float* __restrict__ dst = (sel == 0) ? g_Q : (sel == 1) ? g_K : g_V;
    const int head = (nbase + wn * 64) >> 6;
    const float scale = (sel == 0) ? (1.0f / (8.0f * expf(beta[head]))) : 1.0f;

    #pragma unroll
    for (int mt = 0; mt < 2; mt++) {
        const int m0 = bm * 128 + wm * 32 + mt * 16 + g;   // row for c0,c1
        #pragma unroll
        for (int nt = 0; nt < 8; nt++) {
            const int nm   = nbase + wn * 64 + nt * 8 + t * 2;
            const int dcol = nm & 63;
            const float b0v = bia[nm], b1v = bia[nm + 1];
            #pragma unroll
            for (int half = 0; half < 2; half++) {
                const int m = m0 + half * 8;
                const int s_idx = m >> 1;
                const int b_idx = m & 1;
                float2 o;
                o.x = (acc[mt][nt][half * 2 + 0] + b0v) * scale;
                o.y = (acc[mt][nt][half * 2 + 1] + b1v) * scale;
                *(float2*)&dst[((size_t)(b_idx * NHEADS + head) * S_LEN + s_idx)
                               * DHEAD + dcol] = o;
            }
        }
    }
}

// ---------------------------------------------------------------------------
// Kernel D: dilation pass 0 reduction, partials over 8 s-chunks per z.
// ---------------------------------------------------------------------------
__global__ __launch_bounds__(256) void reduce_kv()
{
    const int z = blockIdx.x;
    const int c = blockIdx.y;
    const int warp = threadIdx.x >> 5;
    const int lane = threadIdx.x & 31;

    const float* __restrict__ Q = g_Q + (size_t)z * S_LEN * DHEAD;
    const float* __restrict__ K = g_K + (size_t)z * S_LEN * DHEAD;
    const float* __restrict__ V = g_V + (size_t)z * S_LEN * DHEAD;

    float k2a = 0.f, k2b = 0.f, v2a = 0.f, v2b = 0.f;
    const int s0 = c * 256;
    for (int s = s0 + warp; s < s0 + 256; s += 8) {
        const float2 qv = *(const float2*)(Q + (size_t)s * DHEAD + lane * 2);
        const float2 kv = *(const float2*)(K + (size_t)s * DHEAD + lane * 2);
        const float2 vv = *(const float2*)(V + (size_t)s * DHEAD + lane * 2);
        float part = qv.x * kv.x + qv.y * kv.y;
        #pragma unroll
        for (int off = 16; off; off >>= 1)
            part += __shfl_xor_sync(0xFFFFFFFFu, part, off);
        const float w = 1.0f / (1.0f + expf(-part));
        k2a = fmaf(w, kv.x, k2a);  k2b = fmaf(w, kv.y, k2b);
        v2a = fmaf(w, vv.x, v2a);  v2b = fmaf(w, vv.y, v2b);
    }

    __shared__ float sk[8][64];
    __shared__ float sv[8][64];
    sk[warp][lane * 2] = k2a;  sk[warp][lane * 2 + 1] = k2b;
    sv[warp][lane * 2] = v2a;  sv[warp][lane * 2 + 1] = v2b;
    __syncthreads();
    if (threadIdx.x < 64) {
        float a = 0.f, b = 0.f;
        #pragma unroll
        for (int w = 0; w < 8; w++) { a += sk[w][threadIdx.x]; b += sv[w][threadIdx.x]; }
        g_k2p[(z * 8 + c) * DHEAD + threadIdx.x] = a;
        g_v2p[(z * 8 + c) * DHEAD + threadIdx.x] = b;
    }
}

// ---------------------------------------------------------------------------
// Kernel E: combine partials + dilation pass 1 (position 2047 only).
// ---------------------------------------------------------------------------
__global__ __launch_bounds__(512) void window_kernel()
{
    __shared__ float s_k2[ZB * DHEAD];
    __shared__ float s_v2[ZB * DHEAD];
    const int tid = threadIdx.x;
    for (int i = tid; i < ZB * DHEAD; i += 512) {
        const int zz = i >> 6, dd = i & 63;
        float a = 0.f, b = 0.f;
        #pragma unroll
        for (int c = 0; c < 8; c++) {
            a += g_k2p[(zz * 8 + c) * DHEAD + dd];
            b += g_v2p[(zz * 8 + c) * DHEAD + dd];
        }
        s_k2[i] = a; s_v2[i] = b;
    }
    __syncthreads();

    const int z    = tid >> 5;
    const int lane = tid & 31;
    const float* __restrict__ q = g_Q + ((size_t)z * S_LEN + (64 * lane + 63)) * DHEAD;
    const float* k2 = s_k2 + z * DHEAD;

    float s = 0.f;
    #pragma unroll
    for (int d = 0; d < DHEAD; d++) s = fmaf(q[d], k2[d], s);

    float mx = s;
    #pragma unroll
    for (int off = 16; off; off >>= 1)
        mx = fmaxf(mx, __shfl_xor_sync(0xFFFFFFFFu, mx, off));
    mx = fmaxf(mx, 0.f);
    const float e = expf(s - mx);
    float sum = e;
    #pragma unroll
    for (int off = 16; off; off >>= 1)
        sum += __shfl_xor_sync(0xFFFFFFFFu, sum, off);
    sum += expf(-mx);
    float cc = e / sum;
    if (lane == 31) cc += 1.0f;

    const int b_idx = z >> 3;
    const int head  = z & 7;
    const float* v2 = s_v2 + z * DHEAD;
    float* __restrict__ row = g_rows + ((size_t)(b_idx * NWIN + lane)) * DMODEL + head * DHEAD;
    #pragma unroll
    for (int d = 0; d < DHEAD; d++) row[d] = cc * v2[d];
}

// ---------------------------------------------------------------------------
__global__ void fill_out(float4* __restrict__ out, const float4* __restrict__ bo4)
{
    int idx = blockIdx.x * blockDim.x + threadIdx.x;
    if (idx < S_LEN * BSZ * DMODEL / 4) out[idx] = bo4[idx & 127];
}

__global__ __launch_bounds__(512) void proj_out(
    float* __restrict__ out,
    const float* __restrict__ Wo,
    const float* __restrict__ bo)
{
    const int wb    = blockIdx.x >> 1;
    const int batch = blockIdx.x & 1;

    __shared__ __align__(16) float in[DMODEL];
    for (int i = threadIdx.x; i < DMODEL; i += blockDim.x)
        in[i] = g_rows[((size_t)(batch * NWIN + wb)) * DMODEL + i];
    __syncthreads();

    const int n = threadIdx.x;
    const float4* __restrict__ w = (const float4*)(Wo + (size_t)n * DMODEL);
    float acc = 0.f;
    #pragma unroll 4
    for (int k4 = 0; k4 < DMODEL / 4; k4++) {
        float4 wv = w[k4];
        const float4 iv = *(const float4*)&in[k4 * 4];
        acc = fmaf(iv.x, wv.x, acc);
        acc = fmaf(iv.y, wv.y, acc);
        acc = fmaf(iv.z, wv.z, acc);
        acc = fmaf(iv.w, wv.w, acc);
    }
    out[((size_t)((2016 + wb) * BSZ + batch)) * DMODEL + n] = acc + bo[n];
}

// ---------------------------------------------------------------------------
extern "C" void kernel_launch(void* const* d_in, const int* in_sizes, int n_in,
                              void* d_out, int out_size)
{
    const float* x    = (const float*)d_in[0];
    const float* Wq   = (const float*)d_in[1];
    const float* bq   = (const float*)d_in[2];
    const float* Wk   = (const float*)d_in[3];
    const float* bk   = (const float*)d_in[4];
    const float* Wv   = (const float*)d_in[5];
    const float* bv   = (const float*)d_in[6];
    const float* Wo   = (const float*)d_in[7];
    const float* bo   = (const float*)d_in[8];
    const float* beta = (const float*)d_in[9];
    float* out = (float*)d_out;

    cudaFuncSetAttribute(gemm_mma, cudaFuncAttributeMaxDynamicSharedMemorySize,
                         SMEM_BYTES);

    convert_x<<<(MROWS * DMODEL + 255) / 256, 256>>>(x);
    convert_w<<<(NTOT * DMODEL + 255) / 256, 256>>>(Wq, Wk, Wv);
    gemm_mma<<<dim3(NTOT / 128, MROWS / 128), 256, SMEM_BYTES>>>(bq, bk, bv, beta);
    reduce_kv<<<dim3(ZB, 8), 256>>>();
    window_kernel<<<1, 512>>>();
    fill_out<<<(S_LEN * BSZ * DMODEL / 4 + 255) / 256, 256>>>((float4*)out, (const float4*)bo);
    proj_out<<<2 * NWIN, 512>>>(out, Wo, bo);
}

// round 4
// speedup vs baseline: 2.4661x; 1.0972x over previous
#include <cuda_runtime.h>
#include <cuda_bf16.h>
#include <math.h>
#include <stdint.h>

#define S_LEN  2048
#define BSZ    2
#define DMODEL 512
#define NHEADS 8
#define DHEAD  64
#define ZB     (BSZ*NHEADS)          // 16
#define MROWS  (S_LEN*BSZ)           // 4096
#define NWIN   32
#define KTOT   1536                  // 3x512 (hi | lo | hi)
#define NTOT   1536                  // Q,K,V columns stacked
#define KC     64                    // K chunk (bf16) = 128B rows
#define NCHUNK (KTOT/KC)             // 24
#define STAGES 3
#define ATILE  16384                 // 128 x 64 bf16
#define BTILE  16384
#define STAGE_BYTES (ATILE+BTILE)
#define SMEM_BYTES  (STAGES*STAGE_BYTES)   // 96 KB
#define RCHUNK 16                    // s-chunks per z in reduce_kv

// ---------------- static scratch (no cudaMalloc allowed) -------------------
__device__ __align__(16) __nv_bfloat16 g_Xc[(size_t)MROWS*KTOT]; // 12.6 MB
__device__ __align__(16) __nv_bfloat16 g_Wc[(size_t)NTOT*KTOT];  //  4.7 MB
__device__ float g_Q[(size_t)ZB*S_LEN*DHEAD];
__device__ float g_K[(size_t)ZB*S_LEN*DHEAD];
__device__ float g_V[(size_t)ZB*S_LEN*DHEAD];
__device__ float g_k2p[ZB*RCHUNK*DHEAD];
__device__ float g_v2p[ZB*RCHUNK*DHEAD];
__device__ float g_rows[BSZ*NWIN*DMODEL];

// ---------------- helpers ---------------------------------------------------
__device__ __forceinline__ uint32_t smem_u32(const void* p) {
    uint32_t a;
    asm("{ .reg .u64 t; cvta.to.shared.u64 t, %1; cvt.u32.u64 %0, t; }"
        : "=r"(a) : "l"(p));
    return a;
}
__device__ __forceinline__ uint32_t swz(uint32_t off) {
    return off ^ ((off >> 3) & 0x70);      // SW128
}
__device__ __forceinline__ void cp16(uint32_t saddr, const void* g) {
    asm volatile("cp.async.cg.shared.global [%0], [%1], 16;"
                 :: "r"(saddr), "l"(g) : "memory");
}
#define CP_COMMIT() asm volatile("cp.async.commit_group;" ::: "memory")
#define CP_WAIT(n)  asm volatile("cp.async.wait_group %0;" :: "n"(n) : "memory")

__device__ __forceinline__ void ldmx4(uint32_t& r0, uint32_t& r1,
                                      uint32_t& r2, uint32_t& r3, uint32_t a) {
    asm volatile("ldmatrix.sync.aligned.m8n8.x4.shared.b16 {%0,%1,%2,%3}, [%4];"
                 : "=r"(r0), "=r"(r1), "=r"(r2), "=r"(r3) : "r"(a));
}
__device__ __forceinline__ void mma16816(float* c, const uint32_t* a,
                                         uint32_t b0, uint32_t b1) {
    asm volatile(
        "mma.sync.aligned.m16n8k16.row.col.f32.bf16.bf16.f32 "
        "{%0,%1,%2,%3}, {%4,%5,%6,%7}, {%8,%9}, {%0,%1,%2,%3};"
        : "+f"(c[0]), "+f"(c[1]), "+f"(c[2]), "+f"(c[3])
        : "r"(a[0]), "r"(a[1]), "r"(a[2]), "r"(a[3]), "r"(b0), "r"(b1));
}

// ---------------------------------------------------------------------------
// Kernel A: fused bf16 hi/lo split for X and W (vectorized: 4 elems/thread).
// Xc[m] = [hi | lo | hi]  (K-split of x),  Wc[n] = [hi | hi | lo].
// ---------------------------------------------------------------------------
__global__ __launch_bounds__(256) void convert_xw(
    const float* __restrict__ x,
    const float* __restrict__ Wq, const float* __restrict__ Wk,
    const float* __restrict__ Wv)
{
    const int tid4 = blockIdx.x * 256 + threadIdx.x;   // index of a float4
    const int XQ4  = MROWS * DMODEL / 4;               // 524288
    const int W4PM = DMODEL / 4;                       // 128 float4 per row

    const float4* src;
    size_t dbase;        // row base in destination (elements)
    int koff;            // element offset of this float4 within the row
    bool isx;
    if (tid4 < XQ4) {
        src  = (const float4*)x + tid4;
        int m = tid4 / W4PM;
        koff  = (tid4 % W4PM) * 4;
        dbase = (size_t)m * KTOT;
        isx = true;
    } else {
        int wi  = tid4 - XQ4;                          // 0 .. NTOT*128-1
        int n   = wi / W4PM;
        koff    = (wi % W4PM) * 4;
        int sel = n >> 9, row = n & 511;
        const float* W = (sel == 0) ? Wq : (sel == 1) ? Wk : Wv;
        src   = (const float4*)(W + (size_t)row * DMODEL + koff);
        dbase = (size_t)n * KTOT;
        isx = false;
    }

    float4 v = *src;
    __nv_bfloat162 hi01 = __nv_bfloat162(__float2bfloat16(v.x), __float2bfloat16(v.y));
    __nv_bfloat162 hi23 = __nv_bfloat162(__float2bfloat16(v.z), __float2bfloat16(v.w));
    __nv_bfloat162 lo01 = __nv_bfloat162(
        __float2bfloat16(v.x - __bfloat162float(hi01.x)),
        __float2bfloat16(v.y - __bfloat162float(hi01.y)));
    __nv_bfloat162 lo23 = __nv_bfloat162(
        __float2bfloat16(v.z - __bfloat162float(hi23.x)),
        __float2bfloat16(v.w - __bfloat162float(hi23.y)));

    __nv_bfloat16* dst = isx ? g_Xc : g_Wc;
    __nv_bfloat162* d0 = (__nv_bfloat162*)(dst + dbase + koff);
    __nv_bfloat162* d1 = (__nv_bfloat162*)(dst + dbase + 512 + koff);
    __nv_bfloat162* d2 = (__nv_bfloat162*)(dst + dbase + 1024 + koff);
    d0[0] = hi01; d0[1] = hi23;
    if (isx) { d1[0] = lo01; d1[1] = lo23; d2[0] = hi01; d2[1] = hi23; }
    else     { d1[0] = hi01; d1[1] = hi23; d2[0] = lo01; d2[1] = lo23; }
}

// ---------------------------------------------------------------------------
// Kernel C: bf16 warp-MMA GEMM  C[4096,1536] = Xc @ Wc^T  (K=1536)
// (unchanged from R3 — passed, ~<27us)
// ---------------------------------------------------------------------------
__global__ __launch_bounds__(256, 2) void gemm_mma(
    const float* __restrict__ bq, const float* __restrict__ bk,
    const float* __restrict__ bv, const float* __restrict__ beta)
{
    extern __shared__ __align__(1024) char smem[];
    const uint32_t sbase = smem_u32(smem);
    const int tid  = threadIdx.x;
    const int lane = tid & 31;
    const int wid  = tid >> 5;
    const int bn = blockIdx.x;           // 0..11
    const int bm = blockIdx.y;           // 0..31

    const __nv_bfloat16* __restrict__ Xb = g_Xc + (size_t)(bm * 128) * KTOT;
    const __nv_bfloat16* __restrict__ Wb = g_Wc + (size_t)(bn * 128) * KTOT;

    const int r0  = tid >> 3;
    const int c16 = tid & 7;
    uint32_t so[4];
    #pragma unroll
    for (int j = 0; j < 4; j++)
        so[j] = swz((uint32_t)((r0 + 32 * j) * 128 + c16 * 16));

    const int wm = wid & 3;
    const int wn = wid >> 2;
    const int g  = lane >> 2;
    const int t  = lane & 3;

    const int a_row = wm * 32 + (lane & 15);
    const int a_kb  = (lane >> 4) * 16;
    const int b_row = wn * 64 + (lane & 7) + (lane >> 4) * 8;
    const int b_kb  = ((lane >> 3) & 1) * 16;

    float acc[2][8][4];
    #pragma unroll
    for (int i = 0; i < 2; i++)
        #pragma unroll
        for (int j = 0; j < 8; j++)
            #pragma unroll
            for (int q = 0; q < 4; q++) acc[i][j][q] = 0.f;

    #pragma unroll
    for (int s = 0; s < STAGES - 1; s++) {
        uint32_t sA = sbase + s * STAGE_BYTES;
        uint32_t sB = sA + ATILE;
        const __nv_bfloat16* gA = Xb + (size_t)s * KC + c16 * 8;
        const __nv_bfloat16* gB = Wb + (size_t)s * KC + c16 * 8;
        #pragma unroll
        for (int j = 0; j < 4; j++) {
            cp16(sA + so[j], gA + (size_t)(r0 + 32 * j) * KTOT);
            cp16(sB + so[j], gB + (size_t)(r0 + 32 * j) * KTOT);
        }
        CP_COMMIT();
    }

    for (int i = 0; i < NCHUNK; i++) {
        CP_WAIT(STAGES - 2);
        __syncthreads();

        const int nxt = i + STAGES - 1;
        if (nxt < NCHUNK) {
            const int st = nxt % STAGES;
            uint32_t sA = sbase + st * STAGE_BYTES;
            uint32_t sB = sA + ATILE;
            const __nv_bfloat16* gA = Xb + (size_t)nxt * KC + c16 * 8;
            const __nv_bfloat16* gB = Wb + (size_t)nxt * KC + c16 * 8;
            #pragma unroll
            for (int j = 0; j < 4; j++) {
                cp16(sA + so[j], gA + (size_t)(r0 + 32 * j) * KTOT);
                cp16(sB + so[j], gB + (size_t)(r0 + 32 * j) * KTOT);
            }
        }
        CP_COMMIT();

        const uint32_t sA = sbase + (i % STAGES) * STAGE_BYTES;
        const uint32_t sB = sA + ATILE;
        #pragma unroll
        for (int k16 = 0; k16 < 4; k16++) {
            uint32_t af[2][4];
            #pragma unroll
            for (int mt = 0; mt < 2; mt++) {
                uint32_t addr = sA + swz((uint32_t)((a_row + mt * 16) * 128
                                                    + k16 * 32 + a_kb));
                ldmx4(af[mt][0], af[mt][1], af[mt][2], af[mt][3], addr);
            }
            uint32_t bf[8][2];
            #pragma unroll
            for (int nt2 = 0; nt2 < 4; nt2++) {
                uint32_t addr = sB + swz((uint32_t)((b_row + nt2 * 16) * 128
                                                    + k16 * 32 + b_kb));
                uint32_t q0, q1, q2, q3;
                ldmx4(q0, q1, q2, q3, addr);
                bf[nt2 * 2 + 0][0] = q0; bf[nt2 * 2 + 0][1] = q1;
                bf[nt2 * 2 + 1][0] = q2; bf[nt2 * 2 + 1][1] = q3;
            }
            #pragma unroll
            for (int mt = 0; mt < 2; mt++)
                #pragma unroll
                for (int nt = 0; nt < 8; nt++)
                    mma16816(acc[mt][nt], af[mt], bf[nt][0], bf[nt][1]);
        }
    }

    const int sel   = bn >> 2;
    const int nbase = (bn & 3) * 128;
    const float* __restrict__ bia = (sel == 0) ? bq : (sel == 1) ? bk : bv;
    float* __restrict__ dst = (sel == 0) ? g_Q : (sel == 1) ? g_K : g_V;
    const int head = (nbase + wn * 64) >> 6;
    const float scale = (sel == 0) ? (1.0f / (8.0f * expf(beta[head]))) : 1.0f;

    #pragma unroll
    for (int mt = 0; mt < 2; mt++) {
        const int m0 = bm * 128 + wm * 32 + mt * 16 + g;
        #pragma unroll
        for (int nt = 0; nt < 8; nt++) {
            const int nm   = nbase + wn * 64 + nt * 8 + t * 2;
            const int dcol = nm & 63;
            const float b0v = bia[nm], b1v = bia[nm + 1];
            #pragma unroll
            for (int half = 0; half < 2; half++) {
                const int m = m0 + half * 8;
                const int s_idx = m >> 1;
                const int b_idx = m & 1;
                float2 o;
                o.x = (acc[mt][nt][half * 2 + 0] + b0v) * scale;
                o.y = (acc[mt][nt][half * 2 + 1] + b1v) * scale;
                *(float2*)&dst[((size_t)(b_idx * NHEADS + head) * S_LEN + s_idx)
                               * DHEAD + dcol] = o;
            }
        }
    }
}

// ---------------------------------------------------------------------------
// Kernel D: dilation pass 0 reduction — quad-per-s layout (2-deep shuffle),
// 16 chunks per z (grid 16x16), 2 s-iterations per thread.
// ---------------------------------------------------------------------------
__global__ __launch_bounds__(256) void reduce_kv()
{
    const int z = blockIdx.x;
    const int c = blockIdx.y;
    const int t = threadIdx.x;
    const int squad = t >> 2;            // 0..63 : s within half-chunk
    const int dpart = (t & 3) * 16;      // 16 d-components per lane

    const float* __restrict__ Q = g_Q + (size_t)z * S_LEN * DHEAD + dpart;
    const float* __restrict__ K = g_K + (size_t)z * S_LEN * DHEAD + dpart;
    const float* __restrict__ V = g_V + (size_t)z * S_LEN * DHEAD + dpart;

    float4 k2[4] = {}, v2[4] = {};
    const int s0 = c * 128;

    #pragma unroll
    for (int it = 0; it < 2; it++) {
        const size_t base = (size_t)(s0 + it * 64 + squad) * DHEAD;
        float4 q4[4], k4[4], v4[4];
        #pragma unroll
        for (int j = 0; j < 4; j++) {
            q4[j] = *(const float4*)(Q + base + j * 4);
            k4[j] = *(const float4*)(K + base + j * 4);
            v4[j] = *(const float4*)(V + base + j * 4);
        }
        float dot = 0.f;
        #pragma unroll
        for (int j = 0; j < 4; j++) {
            dot = fmaf(q4[j].x, k4[j].x, dot);
            dot = fmaf(q4[j].y, k4[j].y, dot);
            dot = fmaf(q4[j].z, k4[j].z, dot);
            dot = fmaf(q4[j].w, k4[j].w, dot);
        }
        dot += __shfl_xor_sync(0xFFFFFFFFu, dot, 1);
        dot += __shfl_xor_sync(0xFFFFFFFFu, dot, 2);
        const float w = 1.0f / (1.0f + expf(-dot));
        #pragma unroll
        for (int j = 0; j < 4; j++) {
            k2[j].x = fmaf(w, k4[j].x, k2[j].x);
            k2[j].y = fmaf(w, k4[j].y, k2[j].y);
            k2[j].z = fmaf(w, k4[j].z, k2[j].z);
            k2[j].w = fmaf(w, k4[j].w, k2[j].w);
            v2[j].x = fmaf(w, v4[j].x, v2[j].x);
            v2[j].y = fmaf(w, v4[j].y, v2[j].y);
            v2[j].z = fmaf(w, v4[j].z, v2[j].z);
            v2[j].w = fmaf(w, v4[j].w, v2[j].w);
        }
    }

    __shared__ float sk[64][64];
    __shared__ float sv[64][64];
    #pragma unroll
    for (int j = 0; j < 4; j++) {
        *(float4*)&sk[squad][dpart + j * 4] = k2[j];
        *(float4*)&sv[squad][dpart + j * 4] = v2[j];
    }
    __syncthreads();

    if (t < 128) {
        const int d = t & 63;
        float acc = 0.f;
        if (t < 64) {
            #pragma unroll 8
            for (int sq = 0; sq < 64; sq++) acc += sk[sq][d];
            g_k2p[(z * RCHUNK + c) * DHEAD + d] = acc;
        } else {
            #pragma unroll 8
            for (int sq = 0; sq < 64; sq++) acc += sv[sq][d];
            g_v2p[(z * RCHUNK + c) * DHEAD + d] = acc;
        }
    }
}

// ---------------------------------------------------------------------------
// Kernel E: combine partials + dilation pass 1 (position 2047 only).
// ---------------------------------------------------------------------------
__global__ __launch_bounds__(512) void window_kernel()
{
    __shared__ float s_k2[ZB * DHEAD];
    __shared__ float s_v2[ZB * DHEAD];
    const int tid = threadIdx.x;
    for (int i = tid; i < ZB * DHEAD; i += 512) {
        const int zz = i >> 6, dd = i & 63;
        float a = 0.f, b = 0.f;
        #pragma unroll
        for (int c = 0; c < RCHUNK; c++) {
            a += g_k2p[(zz * RCHUNK + c) * DHEAD + dd];
            b += g_v2p[(zz * RCHUNK + c) * DHEAD + dd];
        }
        s_k2[i] = a; s_v2[i] = b;
    }
    __syncthreads();

    const int z    = tid >> 5;
    const int lane = tid & 31;
    const float* __restrict__ q = g_Q + ((size_t)z * S_LEN + (64 * lane + 63)) * DHEAD;
    const float* k2 = s_k2 + z * DHEAD;

    float s = 0.f;
    #pragma unroll
    for (int d = 0; d < DHEAD; d++) s = fmaf(q[d], k2[d], s);

    float mx = s;
    #pragma unroll
    for (int off = 16; off; off >>= 1)
        mx = fmaxf(mx, __shfl_xor_sync(0xFFFFFFFFu, mx, off));
    mx = fmaxf(mx, 0.f);
    const float e = expf(s - mx);
    float sum = e;
    #pragma unroll
    for (int off = 16; off; off >>= 1)
        sum += __shfl_xor_sync(0xFFFFFFFFu, sum, off);
    sum += expf(-mx);
    float cc = e / sum;
    if (lane == 31) cc += 1.0f;

    const int b_idx = z >> 3;
    const int head  = z & 7;
    const float* v2 = s_v2 + z * DHEAD;
    float* __restrict__ row = g_rows + ((size_t)(b_idx * NWIN + lane)) * DMODEL + head * DHEAD;
    #pragma unroll
    for (int d = 0; d < DHEAD; d++) row[d] = cc * v2[d];
}

// ---------------------------------------------------------------------------
// Kernel F: bias fill — 4 float4 per thread, bias cached in smem.
// ---------------------------------------------------------------------------
__global__ __launch_bounds__(256) void fill_out(
    float4* __restrict__ out, const float4* __restrict__ bo4)
{
    __shared__ float4 sb[128];
    if (threadIdx.x < 128) sb[threadIdx.x] = bo4[threadIdx.x];
    __syncthreads();
    const int base = blockIdx.x * 1024 + threadIdx.x;
    #pragma unroll
    for (int j = 0; j < 4; j++) {
        const int idx = base + j * 256;
        out[idx] = sb[idx & 127];
    }
}

__global__ __launch_bounds__(512) void proj_out(
    float* __restrict__ out,
    const float* __restrict__ Wo,
    const float* __restrict__ bo)
{
    const int wb    = blockIdx.x >> 1;
    const int batch = blockIdx.x & 1;

    __shared__ __align__(16) float in[DMODEL];
    for (int i = threadIdx.x; i < DMODEL; i += blockDim.x)
        in[i] = g_rows[((size_t)(batch * NWIN + wb)) * DMODEL + i];
    __syncthreads();

    const int n = threadIdx.x;
    const float4* __restrict__ w = (const float4*)(Wo + (size_t)n * DMODEL);
    float acc = 0.f;
    #pragma unroll 4
    for (int k4 = 0; k4 < DMODEL / 4; k4++) {
        float4 wv = w[k4];
        const float4 iv = *(const float4*)&in[k4 * 4];
        acc = fmaf(iv.x, wv.x, acc);
        acc = fmaf(iv.y, wv.y, acc);
        acc = fmaf(iv.z, wv.z, acc);
        acc = fmaf(iv.w, wv.w, acc);
    }
    out[((size_t)((2016 + wb) * BSZ + batch)) * DMODEL + n] = acc + bo[n];
}

// ---------------------------------------------------------------------------
extern "C" void kernel_launch(void* const* d_in, const int* in_sizes, int n_in,
                              void* d_out, int out_size)
{
    const float* x    = (const float*)d_in[0];
    const float* Wq   = (const float*)d_in[1];
    const float* bq   = (const float*)d_in[2];
    const float* Wk   = (const float*)d_in[3];
    const float* bk   = (const float*)d_in[4];
    const float* Wv   = (const float*)d_in[5];
    const float* bv   = (const float*)d_in[6];
    const float* Wo   = (const float*)d_in[7];
    const float* bo   = (const float*)d_in[8];
    const float* beta = (const float*)d_in[9];
    float* out = (float*)d_out;

    cudaFuncSetAttribute(gemm_mma, cudaFuncAttributeMaxDynamicSharedMemorySize,
                         SMEM_BYTES);

    const int conv_blocks = ((MROWS + NTOT) * DMODEL / 4 + 255) / 256;
    convert_xw<<<conv_blocks, 256>>>(x, Wq, Wk, Wv);
    gemm_mma<<<dim3(NTOT / 128, MROWS / 128), 256, SMEM_BYTES>>>(bq, bk, bv, beta);
    reduce_kv<<<dim3(ZB, RCHUNK), 256>>>();
    window_kernel<<<1, 512>>>();
    fill_out<<<(S_LEN * BSZ * DMODEL / 4) / 1024, 256>>>((float4*)out, (const float4*)bo);
    proj_out<<<2 * NWIN, 512>>>(out, Wo, bo);
}

// round 5
// speedup vs baseline: 3.3278x; 1.3494x over previous
#include <cuda_runtime.h>
#include <cuda_bf16.h>
#include <math.h>
#include <stdint.h>

#define S_LEN  2048
#define BSZ    2
#define DMODEL 512
#define NHEADS 8
#define DHEAD  64
#define ZB     (BSZ*NHEADS)          // 16
#define MROWS  (S_LEN*BSZ)           // 4096
#define NWIN   32
#define KSTORE 1024                  // stored K per row: [hi(512) | lo(512)]
#define NTOT   1536                  // Q,K,V columns stacked
#define KC     64                    // K chunk (bf16) = 128B rows
#define NCHUNK 24                    // logical chunks: hi*hi, lo*hi, hi*lo
#define STAGES 3
#define ATILE  16384                 // 128 x 64 bf16
#define BTILE  16384
#define STAGE_BYTES (ATILE+BTILE)
#define SMEM_BYTES  (STAGES*STAGE_BYTES)   // 96 KB
#define RCHUNK 16                    // s-chunks per z in reduce_kv
#define FILL_BLOCKS 504              // 2016*2*512/4 float4 / 1024 per block

// ---------------- static scratch (no cudaMalloc allowed) -------------------
__device__ __align__(16) __nv_bfloat16 g_Xc[(size_t)MROWS*KSTORE]; // 8.4 MB
__device__ __align__(16) __nv_bfloat16 g_Wc[(size_t)NTOT*KSTORE];  // 3.1 MB
__device__ float g_Q[(size_t)ZB*S_LEN*DHEAD];
__device__ float g_K[(size_t)ZB*S_LEN*DHEAD];
__device__ float g_V[(size_t)ZB*S_LEN*DHEAD];
__device__ float g_k2p[ZB*RCHUNK*DHEAD];
__device__ float g_v2p[ZB*RCHUNK*DHEAD];

// ---------------- helpers ---------------------------------------------------
__device__ __forceinline__ uint32_t smem_u32(const void* p) {
    uint32_t a;
    asm("{ .reg .u64 t; cvta.to.shared.u64 t, %1; cvt.u32.u64 %0, t; }"
        : "=r"(a) : "l"(p));
    return a;
}
__device__ __forceinline__ uint32_t swz(uint32_t off) {
    return off ^ ((off >> 3) & 0x70);      // SW128
}
__device__ __forceinline__ void cp16(uint32_t saddr, const void* g) {
    asm volatile("cp.async.cg.shared.global [%0], [%1], 16;"
                 :: "r"(saddr), "l"(g) : "memory");
}
#define CP_COMMIT() asm volatile("cp.async.commit_group;" ::: "memory")
#define CP_WAIT(n)  asm volatile("cp.async.wait_group %0;" :: "n"(n) : "memory")

__device__ __forceinline__ void ldmx4(uint32_t& r0, uint32_t& r1,
                                      uint32_t& r2, uint32_t& r3, uint32_t a) {
    asm volatile("ldmatrix.sync.aligned.m8n8.x4.shared.b16 {%0,%1,%2,%3}, [%4];"
                 : "=r"(r0), "=r"(r1), "=r"(r2), "=r"(r3) : "r"(a));
}
__device__ __forceinline__ void mma16816(float* c, const uint32_t* a,
                                         uint32_t b0, uint32_t b1) {
    asm volatile(
        "mma.sync.aligned.m16n8k16.row.col.f32.bf16.bf16.f32 "
        "{%0,%1,%2,%3}, {%4,%5,%6,%7}, {%8,%9}, {%0,%1,%2,%3};"
        : "+f"(c[0]), "+f"(c[1]), "+f"(c[2]), "+f"(c[3])
        : "r"(a[0]), "r"(a[1]), "r"(a[2]), "r"(a[3]), "r"(b0), "r"(b1));
}

// ---------------------------------------------------------------------------
// Kernel A: bf16 hi/lo split for X and W.  dst row = [hi(512) | lo(512)].
// ---------------------------------------------------------------------------
__global__ __launch_bounds__(256) void convert_xw(
    const float* __restrict__ x,
    const float* __restrict__ Wq, const float* __restrict__ Wk,
    const float* __restrict__ Wv)
{
    const int tid4 = blockIdx.x * 256 + threadIdx.x;   // index of a float4
    const int XQ4  = MROWS * DMODEL / 4;               // 524288
    const int W4PM = DMODEL / 4;                       // 128 float4 per row

    const float4* src;
    __nv_bfloat16* dst;
    size_t dbase;
    int koff;
    if (tid4 < XQ4) {
        src   = (const float4*)x + tid4;
        int m = tid4 / W4PM;
        koff  = (tid4 % W4PM) * 4;
        dbase = (size_t)m * KSTORE;
        dst   = g_Xc;
    } else {
        int wi  = tid4 - XQ4;                          // 0 .. NTOT*128-1
        int n   = wi / W4PM;
        koff    = (wi % W4PM) * 4;
        int sel = n >> 9, row = n & 511;
        const float* W = (sel == 0) ? Wq : (sel == 1) ? Wk : Wv;
        src   = (const float4*)(W + (size_t)row * DMODEL + koff);
        dbase = (size_t)n * KSTORE;
        dst   = g_Wc;
    }

    float4 v = *src;
    __nv_bfloat162 hi01 = __nv_bfloat162(__float2bfloat16(v.x), __float2bfloat16(v.y));
    __nv_bfloat162 hi23 = __nv_bfloat162(__float2bfloat16(v.z), __float2bfloat16(v.w));
    __nv_bfloat162 lo01 = __nv_bfloat162(
        __float2bfloat16(v.x - __bfloat162float(hi01.x)),
        __float2bfloat16(v.y - __bfloat162float(hi01.y)));
    __nv_bfloat162 lo23 = __nv_bfloat162(
        __float2bfloat16(v.z - __bfloat162float(hi23.x)),
        __float2bfloat16(v.w - __bfloat162float(hi23.y)));

    __nv_bfloat162* d0 = (__nv_bfloat162*)(dst + dbase + koff);
    __nv_bfloat162* d1 = (__nv_bfloat162*)(dst + dbase + 512 + koff);
    d0[0] = hi01; d0[1] = hi23;
    d1[0] = lo01; d1[1] = lo23;
}

// ---------------------------------------------------------------------------
// Kernel B: bf16 warp-MMA GEMM  C[4096,1536] = X' @ W'^T  (logical K=1536)
// Chunk mapping gives hi*hi (i<8... wait: i 0-15 ac=i) — see mapping below:
//   ac = i<16 ? i : i-16   (X chunks: hi 0-7, lo 8-15, hi again 16-23)
//   bc = i<8  ? i : i-8    (W chunks: hi 0-7, hi again 8-15, lo 16-23 -> 8-15)
// Products: i 0-7 hi*hi, 8-15 lo*hi, 16-23 hi*lo.
// ---------------------------------------------------------------------------
__global__ __launch_bounds__(256, 2) void gemm_mma(
    const float* __restrict__ bq, const float* __restrict__ bk,
    const float* __restrict__ bv, const float* __restrict__ beta)
{
    extern __shared__ __align__(1024) char smem[];
    const uint32_t sbase = smem_u32(smem);
    const int tid  = threadIdx.x;
    const int lane = tid & 31;
    const int wid  = tid >> 5;
    const int bn = blockIdx.x;           // 0..11
    const int bm = blockIdx.y;           // 0..31

    const __nv_bfloat16* __restrict__ Xb = g_Xc + (size_t)(bm * 128) * KSTORE;
    const __nv_bfloat16* __restrict__ Wb = g_Wc + (size_t)(bn * 128) * KSTORE;

    const int r0  = tid >> 3;
    const int c16 = tid & 7;
    uint32_t so[4];
    #pragma unroll
    for (int j = 0; j < 4; j++)
        so[j] = swz((uint32_t)((r0 + 32 * j) * 128 + c16 * 16));

    const int wm = wid & 3;
    const int wn = wid >> 2;
    const int g  = lane >> 2;
    const int t  = lane & 3;

    const int a_row = wm * 32 + (lane & 15);
    const int a_kb  = (lane >> 4) * 16;
    const int b_row = wn * 64 + (lane & 7) + (lane >> 4) * 8;
    const int b_kb  = ((lane >> 3) & 1) * 16;

    float acc[2][8][4];
    #pragma unroll
    for (int i = 0; i < 2; i++)
        #pragma unroll
        for (int j = 0; j < 8; j++)
            #pragma unroll
            for (int q = 0; q < 4; q++) acc[i][j][q] = 0.f;

    #pragma unroll
    for (int s = 0; s < STAGES - 1; s++) {      // chunks 0,1: ac=bc=s
        uint32_t sA = sbase + s * STAGE_BYTES;
        uint32_t sB = sA + ATILE;
        const __nv_bfloat16* gA = Xb + (size_t)s * KC + c16 * 8;
        const __nv_bfloat16* gB = Wb + (size_t)s * KC + c16 * 8;
        #pragma unroll
        for (int j = 0; j < 4; j++) {
            cp16(sA + so[j], gA + (size_t)(r0 + 32 * j) * KSTORE);
            cp16(sB + so[j], gB + (size_t)(r0 + 32 * j) * KSTORE);
        }
        CP_COMMIT();
    }

    for (int i = 0; i < NCHUNK; i++) {
        CP_WAIT(STAGES - 2);
        __syncthreads();

        const int nxt = i + STAGES - 1;
        if (nxt < NCHUNK) {
            const int ac = (nxt < 16) ? nxt : nxt - 16;
            const int bc = (nxt < 8)  ? nxt : nxt - 8;
            const int st = nxt % STAGES;
            uint32_t sA = sbase + st * STAGE_BYTES;
            uint32_t sB = sA + ATILE;
            const __nv_bfloat16* gA = Xb + (size_t)ac * KC + c16 * 8;
            const __nv_bfloat16* gB = Wb + (size_t)bc * KC + c16 * 8;
            #pragma unroll
            for (int j = 0; j < 4; j++) {
                cp16(sA + so[j], gA + (size_t)(r0 + 32 * j) * KSTORE);
                cp16(sB + so[j], gB + (size_t)(r0 + 32 * j) * KSTORE);
            }
        }
        CP_COMMIT();

        const uint32_t sA = sbase + (i % STAGES) * STAGE_BYTES;
        const uint32_t sB = sA + ATILE;
        #pragma unroll
        for (int k16 = 0; k16 < 4; k16++) {
            uint32_t af[2][4];
            #pragma unroll
            for (int mt = 0; mt < 2; mt++) {
                uint32_t addr = sA + swz((uint32_t)((a_row + mt * 16) * 128
                                                    + k16 * 32 + a_kb));
                ldmx4(af[mt][0], af[mt][1], af[mt][2], af[mt][3], addr);
            }
            uint32_t bf[8][2];
            #pragma unroll
            for (int nt2 = 0; nt2 < 4; nt2++) {
                uint32_t addr = sB + swz((uint32_t)((b_row + nt2 * 16) * 128
                                                    + k16 * 32 + b_kb));
                uint32_t q0, q1, q2, q3;
                ldmx4(q0, q1, q2, q3, addr);
                bf[nt2 * 2 + 0][0] = q0; bf[nt2 * 2 + 0][1] = q1;
                bf[nt2 * 2 + 1][0] = q2; bf[nt2 * 2 + 1][1] = q3;
            }
            #pragma unroll
            for (int mt = 0; mt < 2; mt++)
                #pragma unroll
                for (int nt = 0; nt < 8; nt++)
                    mma16816(acc[mt][nt], af[mt], bf[nt][0], bf[nt][1]);
        }
    }

    const int sel   = bn >> 2;
    const int nbase = (bn & 3) * 128;
    const float* __restrict__ bia = (sel == 0) ? bq : (sel == 1) ? bk : bv;
    float* __restrict__ dst = (sel == 0) ? g_Q : (sel == 1) ? g_K : g_V;
    const int head = (nbase + wn * 64) >> 6;
    const float scale = (sel == 0) ? (1.0f / (8.0f * expf(beta[head]))) : 1.0f;

    #pragma unroll
    for (int mt = 0; mt < 2; mt++) {
        const int m0 = bm * 128 + wm * 32 + mt * 16 + g;
        #pragma unroll
        for (int nt = 0; nt < 8; nt++) {
            const int nm   = nbase + wn * 64 + nt * 8 + t * 2;
            const int dcol = nm & 63;
            const float b0v = bia[nm], b1v = bia[nm + 1];
            #pragma unroll
            for (int half = 0; half < 2; half++) {
                const int m = m0 + half * 8;
                const int s_idx = m >> 1;
                const int b_idx = m & 1;
                float2 o;
                o.x = (acc[mt][nt][half * 2 + 0] + b0v) * scale;
                o.y = (acc[mt][nt][half * 2 + 1] + b1v) * scale;
                *(float2*)&dst[((size_t)(b_idx * NHEADS + head) * S_LEN + s_idx)
                               * DHEAD + dcol] = o;
            }
        }
    }
}

// ---------------------------------------------------------------------------
// Kernel C: dilation pass 0 reduction — quad-per-s layout, 16 chunks per z.
// ---------------------------------------------------------------------------
__global__ __launch_bounds__(256) void reduce_kv()
{
    const int z = blockIdx.x;
    const int c = blockIdx.y;
    const int t = threadIdx.x;
    const int squad = t >> 2;
    const int dpart = (t & 3) * 16;

    const float* __restrict__ Q = g_Q + (size_t)z * S_LEN * DHEAD + dpart;
    const float* __restrict__ K = g_K + (size_t)z * S_LEN * DHEAD + dpart;
    const float* __restrict__ V = g_V + (size_t)z * S_LEN * DHEAD + dpart;

    float4 k2[4] = {}, v2[4] = {};
    const int s0 = c * 128;

    #pragma unroll
    for (int it = 0; it < 2; it++) {
        const size_t base = (size_t)(s0 + it * 64 + squad) * DHEAD;
        float4 q4[4], k4[4], v4[4];
        #pragma unroll
        for (int j = 0; j < 4; j++) {
            q4[j] = *(const float4*)(Q + base + j * 4);
            k4[j] = *(const float4*)(K + base + j * 4);
            v4[j] = *(const float4*)(V + base + j * 4);
        }
        float dot = 0.f;
        #pragma unroll
        for (int j = 0; j < 4; j++) {
            dot = fmaf(q4[j].x, k4[j].x, dot);
            dot = fmaf(q4[j].y, k4[j].y, dot);
            dot = fmaf(q4[j].z, k4[j].z, dot);
            dot = fmaf(q4[j].w, k4[j].w, dot);
        }
        dot += __shfl_xor_sync(0xFFFFFFFFu, dot, 1);
        dot += __shfl_xor_sync(0xFFFFFFFFu, dot, 2);
        const float w = 1.0f / (1.0f + expf(-dot));
        #pragma unroll
        for (int j = 0; j < 4; j++) {
            k2[j].x = fmaf(w, k4[j].x, k2[j].x);
            k2[j].y = fmaf(w, k4[j].y, k2[j].y);
            k2[j].z = fmaf(w, k4[j].z, k2[j].z);
            k2[j].w = fmaf(w, k4[j].w, k2[j].w);
            v2[j].x = fmaf(w, v4[j].x, v2[j].x);
            v2[j].y = fmaf(w, v4[j].y, v2[j].y);
            v2[j].z = fmaf(w, v4[j].z, v2[j].z);
            v2[j].w = fmaf(w, v4[j].w, v2[j].w);
        }
    }

    __shared__ float sk[64][64];
    __shared__ float sv[64][64];
    #pragma unroll
    for (int j = 0; j < 4; j++) {
        *(float4*)&sk[squad][dpart + j * 4] = k2[j];
        *(float4*)&sv[squad][dpart + j * 4] = v2[j];
    }
    __syncthreads();

    if (t < 128) {
        const int d = t & 63;
        float acc = 0.f;
        if (t < 64) {
            #pragma unroll 8
            for (int sq = 0; sq < 64; sq++) acc += sk[sq][d];
            g_k2p[(z * RCHUNK + c) * DHEAD + d] = acc;
        } else {
            #pragma unroll 8
            for (int sq = 0; sq < 64; sq++) acc += sv[sq][d];
            g_v2p[(z * RCHUNK + c) * DHEAD + d] = acc;
        }
    }
}

// ---------------------------------------------------------------------------
// Kernel D: fused epilogue.
//   blocks 0..63   : proj rows — combine partials (redundant per block),
//                    window softmax, row build, out = row @ Wo^T + bo
//                    for positions 2016..2047.
//   blocks 64..567 : bias fill of positions 0..2015.
// ---------------------------------------------------------------------------
__global__ __launch_bounds__(512) void epilogue(
    float* __restrict__ out,
    const float* __restrict__ Wo,
    const float* __restrict__ bo)
{
    const int tid = threadIdx.x;

    if (blockIdx.x >= 64) {
        // ---- fill part: positions 0..2015 --------------------------------
        __shared__ float4 sb[128];
        if (tid < 128) sb[tid] = ((const float4*)bo)[tid];
        __syncthreads();
        const int blk = blockIdx.x - 64;              // 0..503
        float4* out4 = (float4*)out;
        #pragma unroll
        for (int j = 0; j < 2; j++) {
            const int idx = blk * 1024 + j * 512 + tid;
            out4[idx] = sb[idx & 127];
        }
        return;
    }

    // ---- proj part -------------------------------------------------------
    const int batch = blockIdx.x & 1;
    const int wb    = blockIdx.x >> 1;                // window 0..31

    __shared__ float s_k2[8 * DHEAD];                 // this batch's 8 heads
    __shared__ float s_v2[8 * DHEAD];
    __shared__ float s_scr[8][32];
    __shared__ float s_c[8][32];
    __shared__ __align__(16) float s_row[DMODEL];

    // Phase 1: combine partials for z = batch*8 + h.
    {
        const int h = tid >> 6, d = tid & 63;
        const int z = batch * NHEADS + h;
        float a = 0.f, b = 0.f;
        #pragma unroll
        for (int c = 0; c < RCHUNK; c++) {
            a += g_k2p[(z * RCHUNK + c) * DHEAD + d];
            b += g_v2p[(z * RCHUNK + c) * DHEAD + d];
        }
        s_k2[tid] = a; s_v2[tid] = b;
    }
    __syncthreads();

    // Phase 2: scores for all (h, w): 256 tasks x 2 threads (32 dims each).
    {
        const int task = tid >> 1, part = tid & 1;
        const int h = task >> 5, w = task & 31;
        const int z = batch * NHEADS + h;
        const float* __restrict__ q =
            g_Q + ((size_t)z * S_LEN + (64 * w + 63)) * DHEAD + part * 32;
        const float* k2 = s_k2 + h * DHEAD + part * 32;
        float s = 0.f;
        #pragma unroll
        for (int j = 0; j < 8; j++) {
            const float4 qv = *(const float4*)(q + j * 4);
            const float4 kv = *(const float4*)(k2 + j * 4);
            s = fmaf(qv.x, kv.x, s); s = fmaf(qv.y, kv.y, s);
            s = fmaf(qv.z, kv.z, s); s = fmaf(qv.w, kv.w, s);
        }
        s += __shfl_xor_sync(0xFFFFFFFFu, s, 1);
        if (part == 0) s_scr[h][w] = s;
    }
    __syncthreads();

    // Phase 3: softmax with sink per head (warps 0..7).
    if (tid < 256) {
        const int h = tid >> 5, w = tid & 31;
        float s = s_scr[h][w];
        float mx = s;
        #pragma unroll
        for (int off = 16; off; off >>= 1)
            mx = fmaxf(mx, __shfl_xor_sync(0xFFFFFFFFu, mx, off));
        mx = fmaxf(mx, 0.f);
        const float e = expf(s - mx);
        float sum = e;
        #pragma unroll
        for (int off = 16; off; off >>= 1)
            sum += __shfl_xor_sync(0xFFFFFFFFu, sum, off);
        sum += expf(-mx);
        float cc = e / sum;
        if (w == 31) cc += 1.0f;
        s_c[h][w] = cc;
    }
    __syncthreads();

    // Phase 4: build row and project.
    s_row[tid] = s_c[tid >> 6][wb] * s_v2[tid];
    __syncthreads();

    const float4* __restrict__ w4 = (const float4*)(Wo + (size_t)tid * DMODEL);
    float acc = 0.f;
    #pragma unroll 4
    for (int k4 = 0; k4 < DMODEL / 4; k4++) {
        const float4 wv = w4[k4];
        const float4 iv = *(const float4*)&s_row[k4 * 4];
        acc = fmaf(iv.x, wv.x, acc);
        acc = fmaf(iv.y, wv.y, acc);
        acc = fmaf(iv.z, wv.z, acc);
        acc = fmaf(iv.w, wv.w, acc);
    }
    out[((size_t)((2016 + wb) * BSZ + batch)) * DMODEL + tid] = acc + bo[tid];
}

// ---------------------------------------------------------------------------
extern "C" void kernel_launch(void* const* d_in, const int* in_sizes, int n_in,
                              void* d_out, int out_size)
{
    const float* x    = (const float*)d_in[0];
    const float* Wq   = (const float*)d_in[1];
    const float* bq   = (const float*)d_in[2];
    const float* Wk   = (const float*)d_in[3];
    const float* bk   = (const float*)d_in[4];
    const float* Wv   = (const float*)d_in[5];
    const float* bv   = (const float*)d_in[6];
    const float* Wo   = (const float*)d_in[7];
    const float* bo   = (const float*)d_in[8];
    const float* beta = (const float*)d_in[9];
    float* out = (float*)d_out;

    cudaFuncSetAttribute(gemm_mma, cudaFuncAttributeMaxDynamicSharedMemorySize,
                         SMEM_BYTES);

    const int conv_blocks = ((MROWS + NTOT) * DMODEL / 4 + 255) / 256;
    convert_xw<<<conv_blocks, 256>>>(x, Wq, Wk, Wv);
    gemm_mma<<<dim3(NTOT / 128, MROWS / 128), 256, SMEM_BYTES>>>(bq, bk, bv, beta);
    reduce_kv<<<dim3(ZB, RCHUNK), 256>>>();
    epilogue<<<64 + FILL_BLOCKS, 512>>>(out, Wo, bo);
}

// round 6
// speedup vs baseline: 4.4128x; 1.3260x over previous
#include <cuda_runtime.h>
#include <cuda_bf16.h>
#include <math.h>
#include <stdint.h>

#define S_LEN  2048
#define BSZ    2
#define DMODEL 512
#define NHEADS 8
#define DHEAD  64
#define ZB     (BSZ*NHEADS)          // 16
#define MROWS  (S_LEN*BSZ)           // 4096
#define NWIN   32
#define KSTORE 1024                  // stored K per row: [hi(512) | lo(512)]
#define NTOT   1536                  // Q,K,V columns stacked
#define KC     64                    // K chunk (bf16) = 128B rows
#define NCHUNK 24                    // logical chunks: hi*hi, lo*hi, hi*lo
#define STAGES 3
#define ATILE  16384                 // 128 x 64 bf16
#define BTILE  16384
#define STAGE_BYTES (ATILE+BTILE)
#define SMEM_BYTES  (STAGES*STAGE_BYTES)   // 96 KB
#define RCHUNK 16                    // s-chunks per z in reduce_kv
#define CONV_BLOCKS (((MROWS+NTOT)*DMODEL/4)/256)   // 2816
#define FILL_BLOCKS 504              // 2016*2*512/4 float4 / (256 thr * 4)

// ---------------- static scratch (no cudaMalloc allowed) -------------------
__device__ __align__(16) __nv_bfloat16 g_Xc[(size_t)MROWS*KSTORE]; // 8.4 MB
__device__ __align__(16) __nv_bfloat16 g_Wc[(size_t)NTOT*KSTORE];  // 3.1 MB
__device__ float g_Q[(size_t)ZB*S_LEN*DHEAD];
__device__ float g_K[(size_t)ZB*S_LEN*DHEAD];
__device__ float g_V[(size_t)ZB*S_LEN*DHEAD];
__device__ float g_k2p[ZB*RCHUNK*DHEAD];
__device__ float g_v2p[ZB*RCHUNK*DHEAD];

// ---------------- helpers ---------------------------------------------------
__device__ __forceinline__ uint32_t smem_u32(const void* p) {
    uint32_t a;
    asm("{ .reg .u64 t; cvta.to.shared.u64 t, %1; cvt.u32.u64 %0, t; }"
        : "=r"(a) : "l"(p));
    return a;
}
__device__ __forceinline__ uint32_t swz(uint32_t off) {
    return off ^ ((off >> 3) & 0x70);      // SW128
}
__device__ __forceinline__ void cp16(uint32_t saddr, const void* g) {
    asm volatile("cp.async.cg.shared.global [%0], [%1], 16;"
                 :: "r"(saddr), "l"(g) : "memory");
}
#define CP_COMMIT() asm volatile("cp.async.commit_group;" ::: "memory")
#define CP_WAIT(n)  asm volatile("cp.async.wait_group %0;" :: "n"(n) : "memory")

__device__ __forceinline__ void ldmx4(uint32_t& r0, uint32_t& r1,
                                      uint32_t& r2, uint32_t& r3, uint32_t a) {
    asm volatile("ldmatrix.sync.aligned.m8n8.x4.shared.b16 {%0,%1,%2,%3}, [%4];"
                 : "=r"(r0), "=r"(r1), "=r"(r2), "=r"(r3) : "r"(a));
}
__device__ __forceinline__ void mma16816(float* c, const uint32_t* a,
                                         uint32_t b0, uint32_t b1) {
    asm volatile(
        "mma.sync.aligned.m16n8k16.row.col.f32.bf16.bf16.f32 "
        "{%0,%1,%2,%3}, {%4,%5,%6,%7}, {%8,%9}, {%0,%1,%2,%3};"
        : "+f"(c[0]), "+f"(c[1]), "+f"(c[2]), "+f"(c[3])
        : "r"(a[0]), "r"(a[1]), "r"(a[2]), "r"(a[3]), "r"(b0), "r"(b1));
}

// ---------------------------------------------------------------------------
// Kernel A: bf16 hi/lo split for X and W  +  bias fill of out[0..2015].
//   blocks [0, CONV_BLOCKS)                : convert
//   blocks [CONV_BLOCKS, +FILL_BLOCKS)     : fill (independent of converts)
// ---------------------------------------------------------------------------
__global__ __launch_bounds__(256) void convert_xw(
    const float* __restrict__ x,
    const float* __restrict__ Wq, const float* __restrict__ Wk,
    const float* __restrict__ Wv,
    float* __restrict__ out, const float* __restrict__ bo)
{
    if (blockIdx.x >= CONV_BLOCKS) {
        __shared__ float4 sb[128];
        if (threadIdx.x < 128) sb[threadIdx.x] = ((const float4*)bo)[threadIdx.x];
        __syncthreads();
        const int blk = blockIdx.x - CONV_BLOCKS;          // 0..503
        float4* out4 = (float4*)out;
        #pragma unroll
        for (int j = 0; j < 4; j++) {
            const int idx = blk * 1024 + j * 256 + threadIdx.x;
            out4[idx] = sb[idx & 127];
        }
        return;
    }

    const int tid4 = blockIdx.x * 256 + threadIdx.x;   // index of a float4
    const int XQ4  = MROWS * DMODEL / 4;               // 524288
    const int W4PM = DMODEL / 4;                       // 128 float4 per row

    const float4* src;
    __nv_bfloat16* dst;
    size_t dbase;
    int koff;
    if (tid4 < XQ4) {
        src   = (const float4*)x + tid4;
        int m = tid4 / W4PM;
        koff  = (tid4 % W4PM) * 4;
        dbase = (size_t)m * KSTORE;
        dst   = g_Xc;
    } else {
        int wi  = tid4 - XQ4;
        int n   = wi / W4PM;
        koff    = (wi % W4PM) * 4;
        int sel = n >> 9, row = n & 511;
        const float* W = (sel == 0) ? Wq : (sel == 1) ? Wk : Wv;
        src   = (const float4*)(W + (size_t)row * DMODEL + koff);
        dbase = (size_t)n * KSTORE;
        dst   = g_Wc;
    }

    float4 v = *src;
    __nv_bfloat162 hi01 = __nv_bfloat162(__float2bfloat16(v.x), __float2bfloat16(v.y));
    __nv_bfloat162 hi23 = __nv_bfloat162(__float2bfloat16(v.z), __float2bfloat16(v.w));
    __nv_bfloat162 lo01 = __nv_bfloat162(
        __float2bfloat16(v.x - __bfloat162float(hi01.x)),
        __float2bfloat16(v.y - __bfloat162float(hi01.y)));
    __nv_bfloat162 lo23 = __nv_bfloat162(
        __float2bfloat16(v.z - __bfloat162float(hi23.x)),
        __float2bfloat16(v.w - __bfloat162float(hi23.y)));

    __nv_bfloat162* d0 = (__nv_bfloat162*)(dst + dbase + koff);
    __nv_bfloat162* d1 = (__nv_bfloat162*)(dst + dbase + 512 + koff);
    d0[0] = hi01; d0[1] = hi23;
    d1[0] = lo01; d1[1] = lo23;
}

// ---------------------------------------------------------------------------
// Kernel B: bf16 warp-MMA GEMM  C[4096,1536] = X' @ W'^T  (logical K=1536)
//   ac = i<16 ? i : i-16   (X: hi 0-7, lo 8-15)
//   bc = i<8  ? i : i-8    (W: hi 0-7, lo 8-15)
//   i 0-7 hi*hi, 8-15 lo*hi, 16-23 hi*lo.
// ---------------------------------------------------------------------------
__global__ __launch_bounds__(256, 2) void gemm_mma(
    const float* __restrict__ bq, const float* __restrict__ bk,
    const float* __restrict__ bv, const float* __restrict__ beta)
{
    extern __shared__ __align__(1024) char smem[];
    const uint32_t sbase = smem_u32(smem);
    const int tid  = threadIdx.x;
    const int lane = tid & 31;
    const int wid  = tid >> 5;
    const int bn = blockIdx.x;           // 0..11
    const int bm = blockIdx.y;           // 0..31

    const __nv_bfloat16* __restrict__ Xb = g_Xc + (size_t)(bm * 128) * KSTORE;
    const __nv_bfloat16* __restrict__ Wb = g_Wc + (size_t)(bn * 128) * KSTORE;

    const int r0  = tid >> 3;
    const int c16 = tid & 7;
    uint32_t so[4];
    #pragma unroll
    for (int j = 0; j < 4; j++)
        so[j] = swz((uint32_t)((r0 + 32 * j) * 128 + c16 * 16));

    const int wm = wid & 3;
    const int wn = wid >> 2;
    const int g  = lane >> 2;
    const int t  = lane & 3;

    const int a_row = wm * 32 + (lane & 15);
    const int a_kb  = (lane >> 4) * 16;
    const int b_row = wn * 64 + (lane & 7) + (lane >> 4) * 8;
    const int b_kb  = ((lane >> 3) & 1) * 16;

    float acc[2][8][4];
    #pragma unroll
    for (int i = 0; i < 2; i++)
        #pragma unroll
        for (int j = 0; j < 8; j++)
            #pragma unroll
            for (int q = 0; q < 4; q++) acc[i][j][q] = 0.f;

    #pragma unroll
    for (int s = 0; s < STAGES - 1; s++) {      // chunks 0,1: ac=bc=s
        uint32_t sA = sbase + s * STAGE_BYTES;
        uint32_t sB = sA + ATILE;
        const __nv_bfloat16* gA = Xb + (size_t)s * KC + c16 * 8;
        const __nv_bfloat16* gB = Wb + (size_t)s * KC + c16 * 8;
        #pragma unroll
        for (int j = 0; j < 4; j++) {
            cp16(sA + so[j], gA + (size_t)(r0 + 32 * j) * KSTORE);
            cp16(sB + so[j], gB + (size_t)(r0 + 32 * j) * KSTORE);
        }
        CP_COMMIT();
    }

    for (int i = 0; i < NCHUNK; i++) {
        CP_WAIT(STAGES - 2);
        __syncthreads();

        const int nxt = i + STAGES - 1;
        if (nxt < NCHUNK) {
            const int ac = (nxt < 16) ? nxt : nxt - 16;
            const int bc = (nxt < 8)  ? nxt : nxt - 8;
            const int st = nxt % STAGES;
            uint32_t sA = sbase + st * STAGE_BYTES;
            uint32_t sB = sA + ATILE;
            const __nv_bfloat16* gA = Xb + (size_t)ac * KC + c16 * 8;
            const __nv_bfloat16* gB = Wb + (size_t)bc * KC + c16 * 8;
            #pragma unroll
            for (int j = 0; j < 4; j++) {
                cp16(sA + so[j], gA + (size_t)(r0 + 32 * j) * KSTORE);
                cp16(sB + so[j], gB + (size_t)(r0 + 32 * j) * KSTORE);
            }
        }
        CP_COMMIT();

        const uint32_t sA = sbase + (i % STAGES) * STAGE_BYTES;
        const uint32_t sB = sA + ATILE;
        #pragma unroll
        for (int k16 = 0; k16 < 4; k16++) {
            uint32_t af[2][4];
            #pragma unroll
            for (int mt = 0; mt < 2; mt++) {
                uint32_t addr = sA + swz((uint32_t)((a_row + mt * 16) * 128
                                                    + k16 * 32 + a_kb));
                ldmx4(af[mt][0], af[mt][1], af[mt][2], af[mt][3], addr);
            }
            uint32_t bf[8][2];
            #pragma unroll
            for (int nt2 = 0; nt2 < 4; nt2++) {
                uint32_t addr = sB + swz((uint32_t)((b_row + nt2 * 16) * 128
                                                    + k16 * 32 + b_kb));
                uint32_t q0, q1, q2, q3;
                ldmx4(q0, q1, q2, q3, addr);
                bf[nt2 * 2 + 0][0] = q0; bf[nt2 * 2 + 0][1] = q1;
                bf[nt2 * 2 + 1][0] = q2; bf[nt2 * 2 + 1][1] = q3;
            }
            #pragma unroll
            for (int mt = 0; mt < 2; mt++)
                #pragma unroll
                for (int nt = 0; nt < 8; nt++)
                    mma16816(acc[mt][nt], af[mt], bf[nt][0], bf[nt][1]);
        }
    }

    const int sel   = bn >> 2;
    const int nbase = (bn & 3) * 128;
    const float* __restrict__ bia = (sel == 0) ? bq : (sel == 1) ? bk : bv;
    float* __restrict__ dst = (sel == 0) ? g_Q : (sel == 1) ? g_K : g_V;
    const int head = (nbase + wn * 64) >> 6;
    const float scale = (sel == 0) ? (1.0f / (8.0f * expf(beta[head]))) : 1.0f;

    #pragma unroll
    for (int mt = 0; mt < 2; mt++) {
        const int m0 = bm * 128 + wm * 32 + mt * 16 + g;
        #pragma unroll
        for (int nt = 0; nt < 8; nt++) {
            const int nm   = nbase + wn * 64 + nt * 8 + t * 2;
            const int dcol = nm & 63;
            const float b0v = bia[nm], b1v = bia[nm + 1];
            #pragma unroll
            for (int half = 0; half < 2; half++) {
                const int m = m0 + half * 8;
                const int s_idx = m >> 1;
                const int b_idx = m & 1;
                float2 o;
                o.x = (acc[mt][nt][half * 2 + 0] + b0v) * scale;
                o.y = (acc[mt][nt][half * 2 + 1] + b1v) * scale;
                *(float2*)&dst[((size_t)(b_idx * NHEADS + head) * S_LEN + s_idx)
                               * DHEAD + dcol] = o;
            }
        }
    }
}

// ---------------------------------------------------------------------------
// Kernel C: dilation pass 0 reduction — quad-per-s layout, 16 chunks per z.
// ---------------------------------------------------------------------------
__global__ __launch_bounds__(256) void reduce_kv()
{
    const int z = blockIdx.x;
    const int c = blockIdx.y;
    const int t = threadIdx.x;
    const int squad = t >> 2;
    const int dpart = (t & 3) * 16;

    const float* __restrict__ Q = g_Q + (size_t)z * S_LEN * DHEAD + dpart;
    const float* __restrict__ K = g_K + (size_t)z * S_LEN * DHEAD + dpart;
    const float* __restrict__ V = g_V + (size_t)z * S_LEN * DHEAD + dpart;

    float4 k2[4] = {}, v2[4] = {};
    const int s0 = c * 128;

    #pragma unroll
    for (int it = 0; it < 2; it++) {
        const size_t base = (size_t)(s0 + it * 64 + squad) * DHEAD;
        float4 q4[4], k4[4], v4[4];
        #pragma unroll
        for (int j = 0; j < 4; j++) {
            q4[j] = *(const float4*)(Q + base + j * 4);
            k4[j] = *(const float4*)(K + base + j * 4);
            v4[j] = *(const float4*)(V + base + j * 4);
        }
        float dot = 0.f;
        #pragma unroll
        for (int j = 0; j < 4; j++) {
            dot = fmaf(q4[j].x, k4[j].x, dot);
            dot = fmaf(q4[j].y, k4[j].y, dot);
            dot = fmaf(q4[j].z, k4[j].z, dot);
            dot = fmaf(q4[j].w, k4[j].w, dot);
        }
        dot += __shfl_xor_sync(0xFFFFFFFFu, dot, 1);
        dot += __shfl_xor_sync(0xFFFFFFFFu, dot, 2);
        const float w = 1.0f / (1.0f + expf(-dot));
        #pragma unroll
        for (int j = 0; j < 4; j++) {
            k2[j].x = fmaf(w, k4[j].x, k2[j].x);
            k2[j].y = fmaf(w, k4[j].y, k2[j].y);
            k2[j].z = fmaf(w, k4[j].z, k2[j].z);
            k2[j].w = fmaf(w, k4[j].w, k2[j].w);
            v2[j].x = fmaf(w, v4[j].x, v2[j].x);
            v2[j].y = fmaf(w, v4[j].y, v2[j].y);
            v2[j].z = fmaf(w, v4[j].z, v2[j].z);
            v2[j].w = fmaf(w, v4[j].w, v2[j].w);
        }
    }

    __shared__ float sk[64][64];
    __shared__ float sv[64][64];
    #pragma unroll
    for (int j = 0; j < 4; j++) {
        *(float4*)&sk[squad][dpart + j * 4] = k2[j];
        *(float4*)&sv[squad][dpart + j * 4] = v2[j];
    }
    __syncthreads();

    if (t < 128) {
        const int d = t & 63;
        float acc = 0.f;
        if (t < 64) {
            #pragma unroll 8
            for (int sq = 0; sq < 64; sq++) acc += sk[sq][d];
            g_k2p[(z * RCHUNK + c) * DHEAD + d] = acc;
        } else {
            #pragma unroll 8
            for (int sq = 0; sq < 64; sq++) acc += sv[sq][d];
            g_v2p[(z * RCHUNK + c) * DHEAD + d] = acc;
        }
    }
}

// ---------------------------------------------------------------------------
// Kernel D: epilogue — 64 blocks, one (batch, window) output row each.
// Combine partials, window softmax, build row, coalesced row @ Wo^T + bo.
// ---------------------------------------------------------------------------
__global__ __launch_bounds__(512) void epilogue(
    float* __restrict__ out,
    const float* __restrict__ Wo,
    const float* __restrict__ bo)
{
    const int tid   = threadIdx.x;
    const int batch = blockIdx.x & 1;
    const int wb    = blockIdx.x >> 1;                // window 0..31

    __shared__ float s_k2[8 * DHEAD];
    __shared__ float s_v2[8 * DHEAD];
    __shared__ float s_scr[8][32];
    __shared__ float s_c[8][32];
    __shared__ __align__(16) float s_row[DMODEL];

    // Phase 1: combine partials for z = batch*8 + h.
    {
        const int h = tid >> 6, d = tid & 63;
        const int z = batch * NHEADS + h;
        float a = 0.f, b = 0.f;
        #pragma unroll
        for (int c = 0; c < RCHUNK; c++) {
            a += g_k2p[(z * RCHUNK + c) * DHEAD + d];
            b += g_v2p[(z * RCHUNK + c) * DHEAD + d];
        }
        s_k2[tid] = a; s_v2[tid] = b;
    }
    __syncthreads();

    // Phase 2: scores for all (h, w): 256 tasks x 2 threads (32 dims each).
    {
        const int task = tid >> 1, part = tid & 1;
        const int h = task >> 5, w = task & 31;
        const int z = batch * NHEADS + h;
        const float* __restrict__ q =
            g_Q + ((size_t)z * S_LEN + (64 * w + 63)) * DHEAD + part * 32;
        const float* k2 = s_k2 + h * DHEAD + part * 32;
        float s = 0.f;
        #pragma unroll
        for (int j = 0; j < 8; j++) {
            const float4 qv = *(const float4*)(q + j * 4);
            const float4 kv = *(const float4*)(k2 + j * 4);
            s = fmaf(qv.x, kv.x, s); s = fmaf(qv.y, kv.y, s);
            s = fmaf(qv.z, kv.z, s); s = fmaf(qv.w, kv.w, s);
        }
        s += __shfl_xor_sync(0xFFFFFFFFu, s, 1);
        if (part == 0) s_scr[h][w] = s;
    }
    __syncthreads();

    // Phase 3: softmax with sink per head (warps 0..7).
    if (tid < 256) {
        const int h = tid >> 5, w = tid & 31;
        float s = s_scr[h][w];
        float mx = s;
        #pragma unroll
        for (int off = 16; off; off >>= 1)
            mx = fmaxf(mx, __shfl_xor_sync(0xFFFFFFFFu, mx, off));
        mx = fmaxf(mx, 0.f);
        const float e = expf(s - mx);
        float sum = e;
        #pragma unroll
        for (int off = 16; off; off >>= 1)
            sum += __shfl_xor_sync(0xFFFFFFFFu, sum, off);
        sum += expf(-mx);
        float cc = e / sum;
        if (w == 31) cc += 1.0f;
        s_c[h][w] = cc;
    }
    __syncthreads();

    // Phase 4: build row.
    s_row[tid] = s_c[tid >> 6][wb] * s_v2[tid];
    __syncthreads();

    // Phase 5: coalesced projection. Warp w computes outputs n = w*32 + j.
    // For each n, lanes split k: Wo[n][lane*4 + it*128] (float4, coalesced).
    const int warp = tid >> 5;
    const int lane = tid & 31;
    const size_t orow = ((size_t)((2016 + wb) * BSZ + batch)) * DMODEL;

    float4 rv[4];
    #pragma unroll
    for (int it = 0; it < 4; it++)
        rv[it] = *(const float4*)&s_row[it * 128 + lane * 4];

    #pragma unroll 4
    for (int j = 0; j < 32; j++) {
        const int n = warp * 32 + j;
        const float* __restrict__ wrow = Wo + (size_t)n * DMODEL + lane * 4;
        float acc = 0.f;
        #pragma unroll
        for (int it = 0; it < 4; it++) {
            const float4 wv = *(const float4*)(wrow + it * 128);
            acc = fmaf(rv[it].x, wv.x, acc);
            acc = fmaf(rv[it].y, wv.y, acc);
            acc = fmaf(rv[it].z, wv.z, acc);
            acc = fmaf(rv[it].w, wv.w, acc);
        }
        #pragma unroll
        for (int off = 16; off; off >>= 1)
            acc += __shfl_xor_sync(0xFFFFFFFFu, acc, off);
        if (lane == 0) out[orow + n] = acc + bo[n];
    }
}

// ---------------------------------------------------------------------------
extern "C" void kernel_launch(void* const* d_in, const int* in_sizes, int n_in,
                              void* d_out, int out_size)
{
    const float* x    = (const float*)d_in[0];
    const float* Wq   = (const float*)d_in[1];
    const float* bq   = (const float*)d_in[2];
    const float* Wk   = (const float*)d_in[3];
    const float* bk   = (const float*)d_in[4];
    const float* Wv   = (const float*)d_in[5];
    const float* bv   = (const float*)d_in[6];
    const float* Wo   = (const float*)d_in[7];
    const float* bo   = (const float*)d_in[8];
    const float* beta = (const float*)d_in[9];
    float* out = (float*)d_out;

    cudaFuncSetAttribute(gemm_mma, cudaFuncAttributeMaxDynamicSharedMemorySize,
                         SMEM_BYTES);

    convert_xw<<<CONV_BLOCKS + FILL_BLOCKS, 256>>>(x, Wq, Wk, Wv, out, bo);
    gemm_mma<<<dim3(NTOT / 128, MROWS / 128), 256, SMEM_BYTES>>>(bq, bk, bv, beta);
    reduce_kv<<<dim3(ZB, RCHUNK), 256>>>();
    epilogue<<<2 * NWIN, 512>>>(out, Wo, bo);
}

// round 7
// speedup vs baseline: 4.9070x; 1.1120x over previous
#include <cuda_runtime.h>
#include <cuda_bf16.h>
#include <math.h>
#include <stdint.h>

#define S_LEN  2048
#define BSZ    2
#define DMODEL 512
#define NHEADS 8
#define DHEAD  64
#define ZB     (BSZ*NHEADS)          // 16
#define MROWS  (S_LEN*BSZ)           // 4096
#define NWIN   32
#define KSTORE 1024                  // stored K per row: [hi(512) | lo(512)]
#define NTOT   1536                  // Q,K,V columns stacked
#define KC     64                    // K chunk (bf16) = 128B rows
#define NCHUNK 24                    // logical chunks: hi*hi, lo*hi, hi*lo
#define STAGES 3
#define ATILE  16384                 // 128 x 64 bf16
#define BTILE  16384
#define STAGE_BYTES (ATILE+BTILE)
#define SMEM_BYTES  (STAGES*STAGE_BYTES)   // 96 KB
#define RCHUNK 16                    // s-chunks per z in reduce_kv
#define CONV_BLOCKS (((MROWS+NTOT)*DMODEL/4)/256)   // 2816
#define FILL_BLOCKS 504              // 2016*2*512/4 float4 / (256 thr * 4)

// ---------------- static scratch (no cudaMalloc allowed) -------------------
__device__ __align__(16) __nv_bfloat16 g_Xc[(size_t)MROWS*KSTORE]; // 8.4 MB
__device__ __align__(16) __nv_bfloat16 g_Wc[(size_t)NTOT*KSTORE];  // 3.1 MB
__device__ float g_Q[(size_t)ZB*S_LEN*DHEAD];
__device__ float g_K[(size_t)ZB*S_LEN*DHEAD];
__device__ float g_V[(size_t)ZB*S_LEN*DHEAD];
__device__ float g_k2p[ZB*RCHUNK*DHEAD];
__device__ float g_v2p[ZB*RCHUNK*DHEAD];
__device__ float g_P[ZB*DMODEL];     // P[z][n] = v2[z] . Wo[n, h*64 : h*64+64]
__device__ float g_c[ZB*NWIN];       // window coefficients

// ---------------- helpers ---------------------------------------------------
__device__ __forceinline__ uint32_t smem_u32(const void* p) {
    uint32_t a;
    asm("{ .reg .u64 t; cvta.to.shared.u64 t, %1; cvt.u32.u64 %0, t; }"
        : "=r"(a) : "l"(p));
    return a;
}
__device__ __forceinline__ uint32_t swz(uint32_t off) {
    return off ^ ((off >> 3) & 0x70);      // SW128
}
__device__ __forceinline__ void cp16(uint32_t saddr, const void* g) {
    asm volatile("cp.async.cg.shared.global [%0], [%1], 16;"
                 :: "r"(saddr), "l"(g) : "memory");
}
#define CP_COMMIT() asm volatile("cp.async.commit_group;" ::: "memory")
#define CP_WAIT(n)  asm volatile("cp.async.wait_group %0;" :: "n"(n) : "memory")

__device__ __forceinline__ void ldmx4(uint32_t& r0, uint32_t& r1,
                                      uint32_t& r2, uint32_t& r3, uint32_t a) {
    asm volatile("ldmatrix.sync.aligned.m8n8.x4.shared.b16 {%0,%1,%2,%3}, [%4];"
                 : "=r"(r0), "=r"(r1), "=r"(r2), "=r"(r3) : "r"(a));
}
__device__ __forceinline__ void mma16816(float* c, const uint32_t* a,
                                         uint32_t b0, uint32_t b1) {
    asm volatile(
        "mma.sync.aligned.m16n8k16.row.col.f32.bf16.bf16.f32 "
        "{%0,%1,%2,%3}, {%4,%5,%6,%7}, {%8,%9}, {%0,%1,%2,%3};"
        : "+f"(c[0]), "+f"(c[1]), "+f"(c[2]), "+f"(c[3])
        : "r"(a[0]), "r"(a[1]), "r"(a[2]), "r"(a[3]), "r"(b0), "r"(b1));
}

// ---------------------------------------------------------------------------
// Kernel A: bf16 hi/lo split for X and W  +  bias fill of out[0..2015].
// ---------------------------------------------------------------------------
__global__ __launch_bounds__(256) void convert_xw(
    const float* __restrict__ x,
    const float* __restrict__ Wq, const float* __restrict__ Wk,
    const float* __restrict__ Wv,
    float* __restrict__ out, const float* __restrict__ bo)
{
    if (blockIdx.x >= CONV_BLOCKS) {
        __shared__ float4 sb[128];
        if (threadIdx.x < 128) sb[threadIdx.x] = ((const float4*)bo)[threadIdx.x];
        __syncthreads();
        const int blk = blockIdx.x - CONV_BLOCKS;          // 0..503
        float4* out4 = (float4*)out;
        #pragma unroll
        for (int j = 0; j < 4; j++) {
            const int idx = blk * 1024 + j * 256 + threadIdx.x;
            out4[idx] = sb[idx & 127];
        }
        return;
    }

    const int tid4 = blockIdx.x * 256 + threadIdx.x;   // index of a float4
    const int XQ4  = MROWS * DMODEL / 4;               // 524288
    const int W4PM = DMODEL / 4;                       // 128 float4 per row

    const float4* src;
    __nv_bfloat16* dst;
    size_t dbase;
    int koff;
    if (tid4 < XQ4) {
        src   = (const float4*)x + tid4;
        int m = tid4 / W4PM;
        koff  = (tid4 % W4PM) * 4;
        dbase = (size_t)m * KSTORE;
        dst   = g_Xc;
    } else {
        int wi  = tid4 - XQ4;
        int n   = wi / W4PM;
        koff    = (wi % W4PM) * 4;
        int sel = n >> 9, row = n & 511;
        const float* W = (sel == 0) ? Wq : (sel == 1) ? Wk : Wv;
        src   = (const float4*)(W + (size_t)row * DMODEL + koff);
        dbase = (size_t)n * KSTORE;
        dst   = g_Wc;
    }

    float4 v = *src;
    __nv_bfloat162 hi01 = __nv_bfloat162(__float2bfloat16(v.x), __float2bfloat16(v.y));
    __nv_bfloat162 hi23 = __nv_bfloat162(__float2bfloat16(v.z), __float2bfloat16(v.w));
    __nv_bfloat162 lo01 = __nv_bfloat162(
        __float2bfloat16(v.x - __bfloat162float(hi01.x)),
        __float2bfloat16(v.y - __bfloat162float(hi01.y)));
    __nv_bfloat162 lo23 = __nv_bfloat162(
        __float2bfloat16(v.z - __bfloat162float(hi23.x)),
        __float2bfloat16(v.w - __bfloat162float(hi23.y)));

    __nv_bfloat162* d0 = (__nv_bfloat162*)(dst + dbase + koff);
    __nv_bfloat162* d1 = (__nv_bfloat162*)(dst + dbase + 512 + koff);
    d0[0] = hi01; d0[1] = hi23;
    d1[0] = lo01; d1[1] = lo23;
}

// ---------------------------------------------------------------------------
// Kernel B: bf16 warp-MMA GEMM  C[4096,1536] = X' @ W'^T  (logical K=1536)
// ---------------------------------------------------------------------------
__global__ __launch_bounds__(256, 2) void gemm_mma(
    const float* __restrict__ bq, const float* __restrict__ bk,
    const float* __restrict__ bv, const float* __restrict__ beta)
{
    extern __shared__ __align__(1024) char smem[];
    const uint32_t sbase = smem_u32(smem);
    const int tid  = threadIdx.x;
    const int lane = tid & 31;
    const int wid  = tid >> 5;
    const int bn = blockIdx.x;           // 0..11
    const int bm = blockIdx.y;           // 0..31

    const __nv_bfloat16* __restrict__ Xb = g_Xc + (size_t)(bm * 128) * KSTORE;
    const __nv_bfloat16* __restrict__ Wb = g_Wc + (size_t)(bn * 128) * KSTORE;

    const int r0  = tid >> 3;
    const int c16 = tid & 7;
    uint32_t so[4];
    #pragma unroll
    for (int j = 0; j < 4; j++)
        so[j] = swz((uint32_t)((r0 + 32 * j) * 128 + c16 * 16));

    const int wm = wid & 3;
    const int wn = wid >> 2;
    const int g  = lane >> 2;
    const int t  = lane & 3;

    const int a_row = wm * 32 + (lane & 15);
    const int a_kb  = (lane >> 4) * 16;
    const int b_row = wn * 64 + (lane & 7) + (lane >> 4) * 8;
    const int b_kb  = ((lane >> 3) & 1) * 16;

    float acc[2][8][4];
    #pragma unroll
    for (int i = 0; i < 2; i++)
        #pragma unroll
        for (int j = 0; j < 8; j++)
            #pragma unroll
            for (int q = 0; q < 4; q++) acc[i][j][q] = 0.f;

    #pragma unroll
    for (int s = 0; s < STAGES - 1; s++) {
        uint32_t sA = sbase + s * STAGE_BYTES;
        uint32_t sB = sA + ATILE;
        const __nv_bfloat16* gA = Xb + (size_t)s * KC + c16 * 8;
        const __nv_bfloat16* gB = Wb + (size_t)s * KC + c16 * 8;
        #pragma unroll
        for (int j = 0; j < 4; j++) {
            cp16(sA + so[j], gA + (size_t)(r0 + 32 * j) * KSTORE);
            cp16(sB + so[j], gB + (size_t)(r0 + 32 * j) * KSTORE);
        }
        CP_COMMIT();
    }

    for (int i = 0; i < NCHUNK; i++) {
        CP_WAIT(STAGES - 2);
        __syncthreads();

        const int nxt = i + STAGES - 1;
        if (nxt < NCHUNK) {
            const int ac = (nxt < 16) ? nxt : nxt - 16;
            const int bc = (nxt < 8)  ? nxt : nxt - 8;
            const int st = nxt % STAGES;
            uint32_t sA = sbase + st * STAGE_BYTES;
            uint32_t sB = sA + ATILE;
            const __nv_bfloat16* gA = Xb + (size_t)ac * KC + c16 * 8;
            const __nv_bfloat16* gB = Wb + (size_t)bc * KC + c16 * 8;
            #pragma unroll
            for (int j = 0; j < 4; j++) {
                cp16(sA + so[j], gA + (size_t)(r0 + 32 * j) * KSTORE);
                cp16(sB + so[j], gB + (size_t)(r0 + 32 * j) * KSTORE);
            }
        }
        CP_COMMIT();

        const uint32_t sA = sbase + (i % STAGES) * STAGE_BYTES;
        const uint32_t sB = sA + ATILE;
        #pragma unroll
        for (int k16 = 0; k16 < 4; k16++) {
            uint32_t af[2][4];
            #pragma unroll
            for (int mt = 0; mt < 2; mt++) {
                uint32_t addr = sA + swz((uint32_t)((a_row + mt * 16) * 128
                                                    + k16 * 32 + a_kb));
                ldmx4(af[mt][0], af[mt][1], af[mt][2], af[mt][3], addr);
            }
            uint32_t bf[8][2];
            #pragma unroll
            for (int nt2 = 0; nt2 < 4; nt2++) {
                uint32_t addr = sB + swz((uint32_t)((b_row + nt2 * 16) * 128
                                                    + k16 * 32 + b_kb));
                uint32_t q0, q1, q2, q3;
                ldmx4(q0, q1, q2, q3, addr);
                bf[nt2 * 2 + 0][0] = q0; bf[nt2 * 2 + 0][1] = q1;
                bf[nt2 * 2 + 1][0] = q2; bf[nt2 * 2 + 1][1] = q3;
            }
            #pragma unroll
            for (int mt = 0; mt < 2; mt++)
                #pragma unroll
                for (int nt = 0; nt < 8; nt++)
                    mma16816(acc[mt][nt], af[mt], bf[nt][0], bf[nt][1]);
        }
    }

    const int sel   = bn >> 2;
    const int nbase = (bn & 3) * 128;
    const float* __restrict__ bia = (sel == 0) ? bq : (sel == 1) ? bk : bv;
    float* __restrict__ dst = (sel == 0) ? g_Q : (sel == 1) ? g_K : g_V;
    const int head = (nbase + wn * 64) >> 6;
    const float scale = (sel == 0) ? (1.0f / (8.0f * expf(beta[head]))) : 1.0f;

    #pragma unroll
    for (int mt = 0; mt < 2; mt++) {
        const int m0 = bm * 128 + wm * 32 + mt * 16 + g;
        #pragma unroll
        for (int nt = 0; nt < 8; nt++) {
            const int nm   = nbase + wn * 64 + nt * 8 + t * 2;
            const int dcol = nm & 63;
            const float b0v = bia[nm], b1v = bia[nm + 1];
            #pragma unroll
            for (int half = 0; half < 2; half++) {
                const int m = m0 + half * 8;
                const int s_idx = m >> 1;
                const int b_idx = m & 1;
                float2 o;
                o.x = (acc[mt][nt][half * 2 + 0] + b0v) * scale;
                o.y = (acc[mt][nt][half * 2 + 1] + b1v) * scale;
                *(float2*)&dst[((size_t)(b_idx * NHEADS + head) * S_LEN + s_idx)
                               * DHEAD + dcol] = o;
            }
        }
    }
}

// ---------------------------------------------------------------------------
// Kernel C: dilation pass 0 reduction — quad-per-s layout, 16 chunks per z.
// ---------------------------------------------------------------------------
__global__ __launch_bounds__(256) void reduce_kv()
{
    const int z = blockIdx.x;
    const int c = blockIdx.y;
    const int t = threadIdx.x;
    const int squad = t >> 2;
    const int dpart = (t & 3) * 16;

    const float* __restrict__ Q = g_Q + (size_t)z * S_LEN * DHEAD + dpart;
    const float* __restrict__ K = g_K + (size_t)z * S_LEN * DHEAD + dpart;
    const float* __restrict__ V = g_V + (size_t)z * S_LEN * DHEAD + dpart;

    float4 k2[4] = {}, v2[4] = {};
    const int s0 = c * 128;

    #pragma unroll
    for (int it = 0; it < 2; it++) {
        const size_t base = (size_t)(s0 + it * 64 + squad) * DHEAD;
        float4 q4[4], k4[4], v4[4];
        #pragma unroll
        for (int j = 0; j < 4; j++) {
            q4[j] = *(const float4*)(Q + base + j * 4);
            k4[j] = *(const float4*)(K + base + j * 4);
            v4[j] = *(const float4*)(V + base + j * 4);
        }
        float dot = 0.f;
        #pragma unroll
        for (int j = 0; j < 4; j++) {
            dot = fmaf(q4[j].x, k4[j].x, dot);
            dot = fmaf(q4[j].y, k4[j].y, dot);
            dot = fmaf(q4[j].z, k4[j].z, dot);
            dot = fmaf(q4[j].w, k4[j].w, dot);
        }
        dot += __shfl_xor_sync(0xFFFFFFFFu, dot, 1);
        dot += __shfl_xor_sync(0xFFFFFFFFu, dot, 2);
        const float w = 1.0f / (1.0f + expf(-dot));
        #pragma unroll
        for (int j = 0; j < 4; j++) {
            k2[j].x = fmaf(w, k4[j].x, k2[j].x);
            k2[j].y = fmaf(w, k4[j].y, k2[j].y);
            k2[j].z = fmaf(w, k4[j].z, k2[j].z);
            k2[j].w = fmaf(w, k4[j].w, k2[j].w);
            v2[j].x = fmaf(w, v4[j].x, v2[j].x);
            v2[j].y = fmaf(w, v4[j].y, v2[j].y);
            v2[j].z = fmaf(w, v4[j].z, v2[j].z);
            v2[j].w = fmaf(w, v4[j].w, v2[j].w);
        }
    }

    __shared__ float sk[64][64];
    __shared__ float sv[64][64];
    #pragma unroll
    for (int j = 0; j < 4; j++) {
        *(float4*)&sk[squad][dpart + j * 4] = k2[j];
        *(float4*)&sv[squad][dpart + j * 4] = v2[j];
    }
    __syncthreads();

    if (t < 128) {
        const int d = t & 63;
        float acc = 0.f;
        if (t < 64) {
            #pragma unroll 8
            for (int sq = 0; sq < 64; sq++) acc += sk[sq][d];
            g_k2p[(z * RCHUNK + c) * DHEAD + d] = acc;
        } else {
            #pragma unroll 8
            for (int sq = 0; sq < 64; sq++) acc += sv[sq][d];
            g_v2p[(z * RCHUNK + c) * DHEAD + d] = acc;
        }
    }
}

// ---------------------------------------------------------------------------
// Kernel D: coef_proj —
//   blocks [0,256): P[z][n] = v2[z] . Wo[n, h*64 : h*64+64]
//       block (z, nc): z = bid>>4, nc = bid&15 covers n = nc*32 .. +31.
//   blocks [256,272): c[z][w] — combine k2, 32 window scores, sink-softmax.
// ---------------------------------------------------------------------------
__global__ __launch_bounds__(256) void coef_proj(const float* __restrict__ Wo)
{
    const int tid = threadIdx.x;

    if (blockIdx.x < 256) {
        const int z  = blockIdx.x >> 4;
        const int nc = blockIdx.x & 15;
        const int h  = z & 7;

        __shared__ float s_v2[DHEAD];
        if (tid < DHEAD) {
            float a = 0.f;
            #pragma unroll
            for (int c = 0; c < RCHUNK; c++)
                a += g_v2p[(z * RCHUNK + c) * DHEAD + tid];
            s_v2[tid] = a;
        }
        __syncthreads();

        const int warp = tid >> 5;
        const int lane = tid & 31;
        const float2 v2l = *(const float2*)&s_v2[lane * 2];

        #pragma unroll
        for (int j = 0; j < 4; j++) {
            const int n = nc * 32 + warp * 4 + j;
            const float2 wv = *(const float2*)(Wo + (size_t)n * DMODEL
                                               + h * DHEAD + lane * 2);
            float dot = v2l.x * wv.x + v2l.y * wv.y;
            #pragma unroll
            for (int off = 16; off; off >>= 1)
                dot += __shfl_xor_sync(0xFFFFFFFFu, dot, off);
            if (lane == 0) g_P[z * DMODEL + n] = dot;
        }
        return;
    }

    // ---- c-block: one z ----------------------------------------------------
    const int z = blockIdx.x - 256;
    __shared__ float s_k2[DHEAD];
    __shared__ float s_scr[NWIN];

    if (tid < DHEAD) {
        float a = 0.f;
        #pragma unroll
        for (int c = 0; c < RCHUNK; c++)
            a += g_k2p[(z * RCHUNK + c) * DHEAD + tid];
        s_k2[tid] = a;
    }
    __syncthreads();

    {   // scores: w = tid>>3 (0..31), part = tid&7 handles 8 dims
        const int w = tid >> 3, part = tid & 7;
        const float* __restrict__ q =
            g_Q + ((size_t)z * S_LEN + (64 * w + 63)) * DHEAD + part * 8;
        const float4 q0 = *(const float4*)q;
        const float4 q1 = *(const float4*)(q + 4);
        const float4 k0 = *(const float4*)&s_k2[part * 8];
        const float4 k1 = *(const float4*)&s_k2[part * 8 + 4];
        float s = q0.x * k0.x + q0.y * k0.y + q0.z * k0.z + q0.w * k0.w
                + q1.x * k1.x + q1.y * k1.y + q1.z * k1.z + q1.w * k1.w;
        s += __shfl_xor_sync(0xFFFFFFFFu, s, 1);
        s += __shfl_xor_sync(0xFFFFFFFFu, s, 2);
        s += __shfl_xor_sync(0xFFFFFFFFu, s, 4);
        if (part == 0) s_scr[w] = s;
    }
    __syncthreads();

    if (tid < 32) {
        float s = s_scr[tid];
        float mx = s;
        #pragma unroll
        for (int off = 16; off; off >>= 1)
            mx = fmaxf(mx, __shfl_xor_sync(0xFFFFFFFFu, mx, off));
        mx = fmaxf(mx, 0.f);
        const float e = expf(s - mx);
        float sum = e;
        #pragma unroll
        for (int off = 16; off; off >>= 1)
            sum += __shfl_xor_sync(0xFFFFFFFFu, sum, off);
        sum += expf(-mx);
        float cc = e / sum;
        if (tid == 31) cc += 1.0f;
        g_c[z * NWIN + tid] = cc;
    }
}

// ---------------------------------------------------------------------------
// Kernel E: out_rows — out[2016+w, b, n] = bo[n] + sum_h c[b,h,w]*P[b*8+h][n]
// ---------------------------------------------------------------------------
__global__ __launch_bounds__(512) void out_rows(
    float* __restrict__ out, const float* __restrict__ bo)
{
    const int wb    = blockIdx.x >> 1;
    const int batch = blockIdx.x & 1;
    const int n     = threadIdx.x;

    float acc = bo[n];
    #pragma unroll
    for (int h = 0; h < NHEADS; h++) {
        const int z = batch * NHEADS + h;
        acc = fmaf(g_c[z * NWIN + wb], g_P[z * DMODEL + n], acc);
    }
    out[((size_t)((2016 + wb) * BSZ + batch)) * DMODEL + n] = acc;
}

// ---------------------------------------------------------------------------
extern "C" void kernel_launch(void* const* d_in, const int* in_sizes, int n_in,
                              void* d_out, int out_size)
{
    const float* x    = (const float*)d_in[0];
    const float* Wq   = (const float*)d_in[1];
    const float* bq   = (const float*)d_in[2];
    const float* Wk   = (const float*)d_in[3];
    const float* bk   = (const float*)d_in[4];
    const float* Wv   = (const float*)d_in[5];
    const float* bv   = (const float*)d_in[6];
    const float* Wo   = (const float*)d_in[7];
    const float* bo   = (const float*)d_in[8];
    const float* beta = (const float*)d_in[9];
    float* out = (float*)d_out;

    cudaFuncSetAttribute(gemm_mma, cudaFuncAttributeMaxDynamicSharedMemorySize,
                         SMEM_BYTES);

    convert_xw<<<CONV_BLOCKS + FILL_BLOCKS, 256>>>(x, Wq, Wk, Wv, out, bo);
    gemm_mma<<<dim3(NTOT / 128, MROWS / 128), 256, SMEM_BYTES>>>(bq, bk, bv, beta);
    reduce_kv<<<dim3(ZB, RCHUNK), 256>>>();
    coef_proj<<<272, 256>>>(Wo);
    out_rows<<<2 * NWIN, 512>>>(out, bo);
}

// round 8
// speedup vs baseline: 5.8994x; 1.2022x over previous
#include <cuda_runtime.h>
#include <cuda_fp16.h>
#include <math.h>
#include <stdint.h>

#define S_LEN  2048
#define BSZ    2
#define DMODEL 512
#define NHEADS 8
#define DHEAD  64
#define ZB     (BSZ*NHEADS)          // 16
#define MROWS  (S_LEN*BSZ)           // 4096
#define NWIN   32
#define KSX    1024                  // X row: [hi(512) | lo(512)] fp16
#define KSW    512                   // W row: hi only, fp16
#define NTOT   1536                  // Q,K,V columns stacked
#define KC     64                    // K chunk (fp16) = 128B rows
#define NCHUNK 16                    // X hi(8) + lo(8), W hi reused
#define STAGES 3
#define ATILE  16384                 // 128 x 64 fp16
#define BTILE  16384
#define STAGE_BYTES (ATILE+BTILE)
#define SMEM_BYTES  (STAGES*STAGE_BYTES)   // 96 KB
#define RCHUNK 16                    // s-chunks per z in reduce_kv
#define CONV_BLOCKS (((MROWS+NTOT)*DMODEL/4)/256)   // 2816
#define FILL_BLOCKS 504

// ---------------- static scratch (no cudaMalloc allowed) -------------------
__device__ __align__(16) __half g_Xc[(size_t)MROWS*KSX];  // 8.4 MB
__device__ __align__(16) __half g_Wc[(size_t)NTOT*KSW];   // 1.6 MB
__device__ float g_Q[(size_t)ZB*S_LEN*DHEAD];
__device__ float g_K[(size_t)ZB*S_LEN*DHEAD];
__device__ float g_V[(size_t)ZB*S_LEN*DHEAD];
__device__ float g_k2p[ZB*RCHUNK*DHEAD];
__device__ float g_v2p[ZB*RCHUNK*DHEAD];
__device__ float g_k2[ZB*DHEAD];
__device__ float g_v2[ZB*DHEAD];
__device__ int   g_cnt[ZB];          // replay-safe via &15
__device__ float g_P[ZB*DMODEL];
__device__ float g_c[ZB*NWIN];

// ---------------- helpers ---------------------------------------------------
__device__ __forceinline__ uint32_t smem_u32(const void* p) {
    uint32_t a;
    asm("{ .reg .u64 t; cvta.to.shared.u64 t, %1; cvt.u32.u64 %0, t; }"
        : "=r"(a) : "l"(p));
    return a;
}
__device__ __forceinline__ uint32_t swz(uint32_t off) {
    return off ^ ((off >> 3) & 0x70);      // SW128
}
__device__ __forceinline__ void cp16(uint32_t saddr, const void* g) {
    asm volatile("cp.async.cg.shared.global [%0], [%1], 16;"
                 :: "r"(saddr), "l"(g) : "memory");
}
#define CP_COMMIT() asm volatile("cp.async.commit_group;" ::: "memory")
#define CP_WAIT(n)  asm volatile("cp.async.wait_group %0;" :: "n"(n) : "memory")

__device__ __forceinline__ void ldmx4(uint32_t& r0, uint32_t& r1,
                                      uint32_t& r2, uint32_t& r3, uint32_t a) {
    asm volatile("ldmatrix.sync.aligned.m8n8.x4.shared.b16 {%0,%1,%2,%3}, [%4];"
                 : "=r"(r0), "=r"(r1), "=r"(r2), "=r"(r3) : "r"(a));
}
__device__ __forceinline__ void mma16816(float* c, const uint32_t* a,
                                         uint32_t b0, uint32_t b1) {
    asm volatile(
        "mma.sync.aligned.m16n8k16.row.col.f32.f16.f16.f32 "
        "{%0,%1,%2,%3}, {%4,%5,%6,%7}, {%8,%9}, {%0,%1,%2,%3};"
        : "+f"(c[0]), "+f"(c[1]), "+f"(c[2]), "+f"(c[3])
        : "r"(a[0]), "r"(a[1]), "r"(a[2]), "r"(a[3]), "r"(b0), "r"(b1));
}

// ---------------------------------------------------------------------------
// Kernel A: fp16 split X = [hi|lo], W -> hi only  +  bias fill of out rows
// 0..2015.
// ---------------------------------------------------------------------------
__global__ __launch_bounds__(256) void convert_xw(
    const float* __restrict__ x,
    const float* __restrict__ Wq, const float* __restrict__ Wk,
    const float* __restrict__ Wv,
    float* __restrict__ out, const float* __restrict__ bo)
{
    if (blockIdx.x >= CONV_BLOCKS) {
        __shared__ float4 sb[128];
        if (threadIdx.x < 128) sb[threadIdx.x] = ((const float4*)bo)[threadIdx.x];
        __syncthreads();
        const int blk = blockIdx.x - CONV_BLOCKS;          // 0..503
        float4* out4 = (float4*)out;
        #pragma unroll
        for (int j = 0; j < 4; j++) {
            const int idx = blk * 1024 + j * 256 + threadIdx.x;
            out4[idx] = sb[idx & 127];
        }
        return;
    }

    const int tid4 = blockIdx.x * 256 + threadIdx.x;   // index of a float4
    const int XQ4  = MROWS * DMODEL / 4;               // 524288
    const int W4PM = DMODEL / 4;                       // 128 float4 per row

    if (tid4 < XQ4) {
        const float4 v = ((const float4*)x)[tid4];
        const int m    = tid4 / W4PM;
        const int koff = (tid4 % W4PM) * 4;
        const size_t dbase = (size_t)m * KSX;

        __half2 hi01 = __halves2half2(__float2half_rn(v.x), __float2half_rn(v.y));
        __half2 hi23 = __halves2half2(__float2half_rn(v.z), __float2half_rn(v.w));
        __half2 lo01 = __halves2half2(
            __float2half_rn(v.x - __half2float(__low2half(hi01))),
            __float2half_rn(v.y - __half2float(__high2half(hi01))));
        __half2 lo23 = __halves2half2(
            __float2half_rn(v.z - __half2float(__low2half(hi23))),
            __float2half_rn(v.w - __half2float(__high2half(hi23))));

        __half2* d0 = (__half2*)(g_Xc + dbase + koff);
        __half2* d1 = (__half2*)(g_Xc + dbase + 512 + koff);
        d0[0] = hi01; d0[1] = hi23;
        d1[0] = lo01; d1[1] = lo23;
    } else {
        const int wi   = tid4 - XQ4;
        const int n    = wi / W4PM;
        const int koff = (wi % W4PM) * 4;
        const int sel  = n >> 9, row = n & 511;
        const float* W = (sel == 0) ? Wq : (sel == 1) ? Wk : Wv;
        const float4 v = *(const float4*)(W + (size_t)row * DMODEL + koff);

        __half2 hi01 = __halves2half2(__float2half_rn(v.x), __float2half_rn(v.y));
        __half2 hi23 = __halves2half2(__float2half_rn(v.z), __float2half_rn(v.w));
        __half2* d0 = (__half2*)(g_Wc + (size_t)n * KSW + koff);
        d0[0] = hi01; d0[1] = hi23;
    }
}

// ---------------------------------------------------------------------------
// Kernel B: fp16 warp-MMA GEMM  C[4096,1536] = (Xhi+Xlo) @ Whi^T
// 16 chunks: i 0-7 Xhi*Whi, i 8-15 Xlo*Whi  (ac = i, bc = i & 7).
// ---------------------------------------------------------------------------
__global__ __launch_bounds__(256, 2) void gemm_mma(
    const float* __restrict__ bq, const float* __restrict__ bk,
    const float* __restrict__ bv, const float* __restrict__ beta)
{
    extern __shared__ __align__(1024) char smem[];
    const uint32_t sbase = smem_u32(smem);
    const int tid  = threadIdx.x;
    const int lane = tid & 31;
    const int wid  = tid >> 5;
    const int bn = blockIdx.x;           // 0..11
    const int bm = blockIdx.y;           // 0..31

    const __half* __restrict__ Xb = g_Xc + (size_t)(bm * 128) * KSX;
    const __half* __restrict__ Wb = g_Wc + (size_t)(bn * 128) * KSW;

    const int r0  = tid >> 3;
    const int c16 = tid & 7;
    uint32_t so[4];
    #pragma unroll
    for (int j = 0; j < 4; j++)
        so[j] = swz((uint32_t)((r0 + 32 * j) * 128 + c16 * 16));

    const int wm = wid & 3;
    const int wn = wid >> 2;
    const int g  = lane >> 2;
    const int t  = lane & 3;

    const int a_row = wm * 32 + (lane & 15);
    const int a_kb  = (lane >> 4) * 16;
    const int b_row = wn * 64 + (lane & 7) + (lane >> 4) * 8;
    const int b_kb  = ((lane >> 3) & 1) * 16;

    float acc[2][8][4];
    #pragma unroll
    for (int i = 0; i < 2; i++)
        #pragma unroll
        for (int j = 0; j < 8; j++)
            #pragma unroll
            for (int q = 0; q < 4; q++) acc[i][j][q] = 0.f;

    #pragma unroll
    for (int s = 0; s < STAGES - 1; s++) {      // chunks 0,1: ac=bc=s
        uint32_t sA = sbase + s * STAGE_BYTES;
        uint32_t sB = sA + ATILE;
        const __half* gA = Xb + (size_t)s * KC + c16 * 8;
        const __half* gB = Wb + (size_t)s * KC + c16 * 8;
        #pragma unroll
        for (int j = 0; j < 4; j++) {
            cp16(sA + so[j], gA + (size_t)(r0 + 32 * j) * KSX);
            cp16(sB + so[j], gB + (size_t)(r0 + 32 * j) * KSW);
        }
        CP_COMMIT();
    }

    for (int i = 0; i < NCHUNK; i++) {
        CP_WAIT(STAGES - 2);
        __syncthreads();

        const int nxt = i + STAGES - 1;
        if (nxt < NCHUNK) {
            const int ac = nxt;
            const int bc = nxt & 7;
            const int st = nxt % STAGES;
            uint32_t sA = sbase + st * STAGE_BYTES;
            uint32_t sB = sA + ATILE;
            const __half* gA = Xb + (size_t)ac * KC + c16 * 8;
            const __half* gB = Wb + (size_t)bc * KC + c16 * 8;
            #pragma unroll
            for (int j = 0; j < 4; j++) {
                cp16(sA + so[j], gA + (size_t)(r0 + 32 * j) * KSX);
                cp16(sB + so[j], gB + (size_t)(r0 + 32 * j) * KSW);
            }
        }
        CP_COMMIT();

        const uint32_t sA = sbase + (i % STAGES) * STAGE_BYTES;
        const uint32_t sB = sA + ATILE;
        #pragma unroll
        for (int k16 = 0; k16 < 4; k16++) {
            uint32_t af[2][4];
            #pragma unroll
            for (int mt = 0; mt < 2; mt++) {
                uint32_t addr = sA + swz((uint32_t)((a_row + mt * 16) * 128
                                                    + k16 * 32 + a_kb));
                ldmx4(af[mt][0], af[mt][1], af[mt][2], af[mt][3], addr);
            }
            uint32_t bf[8][2];
            #pragma unroll
            for (int nt2 = 0; nt2 < 4; nt2++) {
                uint32_t addr = sB + swz((uint32_t)((b_row + nt2 * 16) * 128
                                                    + k16 * 32 + b_kb));
                uint32_t q0, q1, q2, q3;
                ldmx4(q0, q1, q2, q3, addr);
                bf[nt2 * 2 + 0][0] = q0; bf[nt2 * 2 + 0][1] = q1;
                bf[nt2 * 2 + 1][0] = q2; bf[nt2 * 2 + 1][1] = q3;
            }
            #pragma unroll
            for (int mt = 0; mt < 2; mt++)
                #pragma unroll
                for (int nt = 0; nt < 8; nt++)
                    mma16816(acc[mt][nt], af[mt], bf[nt][0], bf[nt][1]);
        }
    }

    const int sel   = bn >> 2;
    const int nbase = (bn & 3) * 128;
    const float* __restrict__ bia = (sel == 0) ? bq : (sel == 1) ? bk : bv;
    float* __restrict__ dst = (sel == 0) ? g_Q : (sel == 1) ? g_K : g_V;
    const int head = (nbase + wn * 64) >> 6;
    const float scale = (sel == 0) ? (1.0f / (8.0f * expf(beta[head]))) : 1.0f;

    #pragma unroll
    for (int mt = 0; mt < 2; mt++) {
        const int m0 = bm * 128 + wm * 32 + mt * 16 + g;
        #pragma unroll
        for (int nt = 0; nt < 8; nt++) {
            const int nm   = nbase + wn * 64 + nt * 8 + t * 2;
            const int dcol = nm & 63;
            const float b0v = bia[nm], b1v = bia[nm + 1];
            #pragma unroll
            for (int half = 0; half < 2; half++) {
                const int m = m0 + half * 8;
                const int s_idx = m >> 1;
                const int b_idx = m & 1;
                float2 o;
                o.x = (acc[mt][nt][half * 2 + 0] + b0v) * scale;
                o.y = (acc[mt][nt][half * 2 + 1] + b1v) * scale;
                *(float2*)&dst[((size_t)(b_idx * NHEADS + head) * S_LEN + s_idx)
                               * DHEAD + dcol] = o;
            }
        }
    }
}

// ---------------------------------------------------------------------------
// Kernel C: dilation pass 0 reduction; last block per z combines partials.
// ---------------------------------------------------------------------------
__global__ __launch_bounds__(256) void reduce_kv()
{
    const int z = blockIdx.x;
    const int c = blockIdx.y;
    const int t = threadIdx.x;
    const int squad = t >> 2;
    const int dpart = (t & 3) * 16;

    const float* __restrict__ Q = g_Q + (size_t)z * S_LEN * DHEAD + dpart;
    const float* __restrict__ K = g_K + (size_t)z * S_LEN * DHEAD + dpart;
    const float* __restrict__ V = g_V + (size_t)z * S_LEN * DHEAD + dpart;

    float4 k2[4] = {}, v2[4] = {};
    const int s0 = c * 128;

    #pragma unroll
    for (int it = 0; it < 2; it++) {
        const size_t base = (size_t)(s0 + it * 64 + squad) * DHEAD;
        float4 q4[4], k4[4], v4[4];
        #pragma unroll
        for (int j = 0; j < 4; j++) {
            q4[j] = *(const float4*)(Q + base + j * 4);
            k4[j] = *(const float4*)(K + base + j * 4);
            v4[j] = *(const float4*)(V + base + j * 4);
        }
        float dot = 0.f;
        #pragma unroll
        for (int j = 0; j < 4; j++) {
            dot = fmaf(q4[j].x, k4[j].x, dot);
            dot = fmaf(q4[j].y, k4[j].y, dot);
            dot = fmaf(q4[j].z, k4[j].z, dot);
            dot = fmaf(q4[j].w, k4[j].w, dot);
        }
        dot += __shfl_xor_sync(0xFFFFFFFFu, dot, 1);
        dot += __shfl_xor_sync(0xFFFFFFFFu, dot, 2);
        const float w = 1.0f / (1.0f + expf(-dot));
        #pragma unroll
        for (int j = 0; j < 4; j++) {
            k2[j].x = fmaf(w, k4[j].x, k2[j].x);
            k2[j].y = fmaf(w, k4[j].y, k2[j].y);
            k2[j].z = fmaf(w, k4[j].z, k2[j].z);
            k2[j].w = fmaf(w, k4[j].w, k2[j].w);
            v2[j].x = fmaf(w, v4[j].x, v2[j].x);
            v2[j].y = fmaf(w, v4[j].y, v2[j].y);
            v2[j].z = fmaf(w, v4[j].z, v2[j].z);
            v2[j].w = fmaf(w, v4[j].w, v2[j].w);
        }
    }

    __shared__ float sk[64][64];
    __shared__ float sv[64][64];
    #pragma unroll
    for (int j = 0; j < 4; j++) {
        *(float4*)&sk[squad][dpart + j * 4] = k2[j];
        *(float4*)&sv[squad][dpart + j * 4] = v2[j];
    }
    __syncthreads();

    if (t < 128) {
        const int d = t & 63;
        float acc = 0.f;
        if (t < 64) {
            #pragma unroll 8
            for (int sq = 0; sq < 64; sq++) acc += sk[sq][d];
            g_k2p[(z * RCHUNK + c) * DHEAD + d] = acc;
        } else {
            #pragma unroll 8
            for (int sq = 0; sq < 64; sq++) acc += sv[sq][d];
            g_v2p[(z * RCHUNK + c) * DHEAD + d] = acc;
        }
    }
    __syncthreads();

    // Last block per z combines the 16 partials (threadfence reduction).
    __shared__ int s_last;
    if (t == 0) {
        __threadfence();
        const int old = atomicAdd(&g_cnt[z], 1);
        s_last = ((old & (RCHUNK - 1)) == (RCHUNK - 1)) ? 1 : 0;
        if (s_last) __threadfence();
    }
    __syncthreads();
    if (s_last && t < 128) {
        const int d = t & 63;
        float acc = 0.f;
        if (t < 64) {
            #pragma unroll
            for (int cc = 0; cc < RCHUNK; cc++)
                acc += g_k2p[(z * RCHUNK + cc) * DHEAD + d];
            g_k2[z * DHEAD + d] = acc;
        } else {
            #pragma unroll
            for (int cc = 0; cc < RCHUNK; cc++)
                acc += g_v2p[(z * RCHUNK + cc) * DHEAD + d];
            g_v2[z * DHEAD + d] = acc;
        }
    }
}

// ---------------------------------------------------------------------------
// Kernel D: coef_proj —
//   blocks [0,256): P[z][n] = v2[z] . Wo[n, h*64 : h*64+64]
//   blocks [256,272): c[z][w] — 32 window scores + sink-softmax per z.
// ---------------------------------------------------------------------------
__global__ __launch_bounds__(256) void coef_proj(const float* __restrict__ Wo)
{
    const int tid = threadIdx.x;

    if (blockIdx.x < 256) {
        const int z  = blockIdx.x >> 4;
        const int nc = blockIdx.x & 15;
        const int h  = z & 7;

        __shared__ float s_v2[DHEAD];
        if (tid < DHEAD) s_v2[tid] = g_v2[z * DHEAD + tid];
        __syncthreads();

        const int warp = tid >> 5;
        const int lane = tid & 31;
        const float2 v2l = *(const float2*)&s_v2[lane * 2];

        #pragma unroll
        for (int j = 0; j < 4; j++) {
            const int n = nc * 32 + warp * 4 + j;
            const float2 wv = *(const float2*)(Wo + (size_t)n * DMODEL
                                               + h * DHEAD + lane * 2);
            float dot = v2l.x * wv.x + v2l.y * wv.y;
            #pragma unroll
            for (int off = 16; off; off >>= 1)
                dot += __shfl_xor_sync(0xFFFFFFFFu, dot, off);
            if (lane == 0) g_P[z * DMODEL + n] = dot;
        }
        return;
    }

    // ---- c-block: one z ----------------------------------------------------
    const int z = blockIdx.x - 256;
    __shared__ float s_k2[DHEAD];
    __shared__ float s_scr[NWIN];

    if (tid < DHEAD) s_k2[tid] = g_k2[z * DHEAD + tid];
    __syncthreads();

    {   // scores: w = tid>>3 (0..31), part = tid&7 handles 8 dims
        const int w = tid >> 3, part = tid & 7;
        const float* __restrict__ q =
            g_Q + ((size_t)z * S_LEN + (64 * w + 63)) * DHEAD + part * 8;
        const float4 q0 = *(const float4*)q;
        const float4 q1 = *(const float4*)(q + 4);
        const float4 k0 = *(const float4*)&s_k2[part * 8];
        const float4 k1 = *(const float4*)&s_k2[part * 8 + 4];
        float s = q0.x * k0.x + q0.y * k0.y + q0.z * k0.z + q0.w * k0.w
                + q1.x * k1.x + q1.y * k1.y + q1.z * k1.z + q1.w * k1.w;
        s += __shfl_xor_sync(0xFFFFFFFFu, s, 1);
        s += __shfl_xor_sync(0xFFFFFFFFu, s, 2);
        s += __shfl_xor_sync(0xFFFFFFFFu, s, 4);
        if (part == 0) s_scr[w] = s;
    }
    __syncthreads();

    if (tid < 32) {
        float s = s_scr[tid];
        float mx = s;
        #pragma unroll
        for (int off = 16; off; off >>= 1)
            mx = fmaxf(mx, __shfl_xor_sync(0xFFFFFFFFu, mx, off));
        mx = fmaxf(mx, 0.f);
        const float e = expf(s - mx);
        float sum = e;
        #pragma unroll
        for (int off = 16; off; off >>= 1)
            sum += __shfl_xor_sync(0xFFFFFFFFu, sum, off);
        sum += expf(-mx);
        float cc = e / sum;
        if (tid == 31) cc += 1.0f;
        g_c[z * NWIN + tid] = cc;
    }
}

// ---------------------------------------------------------------------------
// Kernel E: out_rows — out[2016+w, b, n] = bo[n] + sum_h c[b,h,w]*P[b*8+h][n]
// ---------------------------------------------------------------------------
__global__ __launch_bounds__(512) void out_rows(
    float* __restrict__ out, const float* __restrict__ bo)
{
    const int wb    = blockIdx.x >> 1;
    const int batch = blockIdx.x & 1;
    const int n     = threadIdx.x;

    float acc = bo[n];
    #pragma unroll
    for (int h = 0; h < NHEADS; h++) {
        const int z = batch * NHEADS + h;
        acc = fmaf(g_c[z * NWIN + wb], g_P[z * DMODEL + n], acc);
    }
    out[((size_t)((2016 + wb) * BSZ + batch)) * DMODEL + n] = acc;
}

// ---------------------------------------------------------------------------
extern "C" void kernel_launch(void* const* d_in, const int* in_sizes, int n_in,
                              void* d_out, int out_size)
{
    const float* x    = (const float*)d_in[0];
    const float* Wq   = (const float*)d_in[1];
    const float* bq   = (const float*)d_in[2];
    const float* Wk   = (const float*)d_in[3];
    const float* bk   = (const float*)d_in[4];
    const float* Wv   = (const float*)d_in[5];
    const float* bv   = (const float*)d_in[6];
    const float* Wo   = (const float*)d_in[7];
    const float* bo   = (const float*)d_in[8];
    const float* beta = (const float*)d_in[9];
    float* out = (float*)d_out;

    cudaFuncSetAttribute(gemm_mma, cudaFuncAttributeMaxDynamicSharedMemorySize,
                         SMEM_BYTES);

    convert_xw<<<CONV_BLOCKS + FILL_BLOCKS, 256>>>(x, Wq, Wk, Wv, out, bo);
    gemm_mma<<<dim3(NTOT / 128, MROWS / 128), 256, SMEM_BYTES>>>(bq, bk, bv, beta);
    reduce_kv<<<dim3(ZB, RCHUNK), 256>>>();
    coef_proj<<<272, 256>>>(Wo);
    out_rows<<<2 * NWIN, 512>>>(out, bo);
}

// round 10
// speedup vs baseline: 5.9183x; 1.0032x over previous
#include <cuda_runtime.h>
#include <cuda_fp16.h>
#include <math.h>
#include <stdint.h>

#define S_LEN  2048
#define BSZ    2
#define DMODEL 512
#define NHEADS 8
#define DHEAD  64
#define ZB     (BSZ*NHEADS)          // 16
#define MROWS  (S_LEN*BSZ)           // 4096
#define NWIN   32
#define KSX    1024                  // X row: [hi(512) | lo(512)] fp16
#define KSW    512                   // W row: hi only, fp16
#define NTOT   1536                  // Q,K,V columns stacked
#define KC     64                    // K chunk (fp16) = 128B rows
#define NCHUNK 16                    // Q,K: hi(8)+lo(8);  V: hi(8) only
#define STAGES 3
#define ATILE  16384                 // 128 x 64 fp16
#define BTILE  16384
#define STAGE_BYTES (ATILE+BTILE)
#define SMEM_BYTES  (STAGES*STAGE_BYTES)   // 96 KB
#define RCHUNK 16                    // s-chunks per z in reduce_kv
#define CONV_BLOCKS (((MROWS+NTOT)*DMODEL/4)/256)   // 2816
#define FILL_BLOCKS 504

// ---------------- static scratch (no cudaMalloc allowed) -------------------
__device__ __align__(16) __half g_Xc[(size_t)MROWS*KSX];  // 8.4 MB
__device__ __align__(16) __half g_Wc[(size_t)NTOT*KSW];   // 1.6 MB
__device__ __align__(16) float g_Q[(size_t)ZB*S_LEN*DHEAD];
__device__ __align__(16) float g_K[(size_t)ZB*S_LEN*DHEAD];
__device__ __align__(16) float g_V[(size_t)ZB*S_LEN*DHEAD];
__device__ __align__(16) float g_k2p[ZB*RCHUNK*DHEAD];
__device__ __align__(16) float g_v2p[ZB*RCHUNK*DHEAD];
__device__ __align__(16) float g_k2[ZB*DHEAD];
__device__ __align__(16) float g_v2[ZB*DHEAD];
__device__ int   g_cnt[ZB];          // replay-safe via &15
__device__ int   g_done;             // reset by reduce_kv each launch
__device__ __align__(16) float g_P[ZB*DMODEL];
__device__ __align__(16) float g_c[ZB*NWIN];

// ---------------- helpers ---------------------------------------------------
__device__ __forceinline__ uint32_t smem_u32(const void* p) {
    uint32_t a;
    asm("{ .reg .u64 t; cvta.to.shared.u64 t, %1; cvt.u32.u64 %0, t; }"
        : "=r"(a) : "l"(p));
    return a;
}
__device__ __forceinline__ uint32_t swz(uint32_t off) {
    return off ^ ((off >> 3) & 0x70);      // SW128
}
__device__ __forceinline__ void cp16(uint32_t saddr, const void* g) {
    asm volatile("cp.async.cg.shared.global [%0], [%1], 16;"
                 :: "r"(saddr), "l"(g) : "memory");
}
#define CP_COMMIT() asm volatile("cp.async.commit_group;" ::: "memory")
#define CP_WAIT(n)  asm volatile("cp.async.wait_group %0;" :: "n"(n) : "memory")

__device__ __forceinline__ void ldmx4(uint32_t& r0, uint32_t& r1,
                                      uint32_t& r2, uint32_t& r3, uint32_t a) {
    asm volatile("ldmatrix.sync.aligned.m8n8.x4.shared.b16 {%0,%1,%2,%3}, [%4];"
                 : "=r"(r0), "=r"(r1), "=r"(r2), "=r"(r3) : "r"(a));
}
__device__ __forceinline__ void mma16816(float* c, const uint32_t* a,
                                         uint32_t b0, uint32_t b1) {
    asm volatile(
        "mma.sync.aligned.m16n8k16.row.col.f32.f16.f16.f32 "
        "{%0,%1,%2,%3}, {%4,%5,%6,%7}, {%8,%9}, {%0,%1,%2,%3};"
        : "+f"(c[0]), "+f"(c[1]), "+f"(c[2]), "+f"(c[3])
        : "r"(a[0]), "r"(a[1]), "r"(a[2]), "r"(a[3]), "r"(b0), "r"(b1));
}

// ---------------------------------------------------------------------------
// Kernel A: fp16 split X = [hi|lo], W -> hi only  +  bias fill rows 0..2015.
// ---------------------------------------------------------------------------
__global__ __launch_bounds__(256) void convert_xw(
    const float* __restrict__ x,
    const float* __restrict__ Wq, const float* __restrict__ Wk,
    const float* __restrict__ Wv,
    float* __restrict__ out, const float* __restrict__ bo)
{
    if (blockIdx.x >= CONV_BLOCKS) {
        __shared__ __align__(16) float4 sb[128];
        if (threadIdx.x < 128) sb[threadIdx.x] = ((const float4*)bo)[threadIdx.x];
        __syncthreads();
        const int blk = blockIdx.x - CONV_BLOCKS;          // 0..503
        float4* out4 = (float4*)out;
        #pragma unroll
        for (int j = 0; j < 4; j++) {
            const int idx = blk * 1024 + j * 256 + threadIdx.x;
            out4[idx] = sb[idx & 127];
        }
        return;
    }

    const int tid4 = blockIdx.x * 256 + threadIdx.x;
    const int XQ4  = MROWS * DMODEL / 4;               // 524288
    const int W4PM = DMODEL / 4;                       // 128 float4 per row

    if (tid4 < XQ4) {
        const float4 v = ((const float4*)x)[tid4];
        const int m    = tid4 / W4PM;
        const int koff = (tid4 % W4PM) * 4;
        const size_t dbase = (size_t)m * KSX;

        __half2 hi01 = __halves2half2(__float2half_rn(v.x), __float2half_rn(v.y));
        __half2 hi23 = __halves2half2(__float2half_rn(v.z), __float2half_rn(v.w));
        __half2 lo01 = __halves2half2(
            __float2half_rn(v.x - __half2float(__low2half(hi01))),
            __float2half_rn(v.y - __half2float(__high2half(hi01))));
        __half2 lo23 = __halves2half2(
            __float2half_rn(v.z - __half2float(__low2half(hi23))),
            __float2half_rn(v.w - __half2float(__high2half(hi23))));

        __half2* d0 = (__half2*)(g_Xc + dbase + koff);
        __half2* d1 = (__half2*)(g_Xc + dbase + 512 + koff);
        d0[0] = hi01; d0[1] = hi23;
        d1[0] = lo01; d1[1] = lo23;
    } else {
        const int wi   = tid4 - XQ4;
        const int n    = wi / W4PM;
        const int koff = (wi % W4PM) * 4;
        const int sel  = n >> 9, row = n & 511;
        const float* W = (sel == 0) ? Wq : (sel == 1) ? Wk : Wv;
        const float4 v = *(const float4*)(W + (size_t)row * DMODEL + koff);

        __half2 hi01 = __halves2half2(__float2half_rn(v.x), __float2half_rn(v.y));
        __half2 hi23 = __halves2half2(__float2half_rn(v.z), __float2half_rn(v.w));
        __half2* d0 = (__half2*)(g_Wc + (size_t)n * KSW + koff);
        d0[0] = hi01; d0[1] = hi23;
    }
}

// ---------------------------------------------------------------------------
// Kernel B: fp16 warp-MMA GEMM.  Q,K blocks: 16 chunks (Xhi+Xlo)@Whi.
// V blocks (sel==2): 8 chunks (Xhi only) — V error is strictly linear.
// ---------------------------------------------------------------------------
__global__ __launch_bounds__(256, 2) void gemm_mma(
    const float* __restrict__ bq, const float* __restrict__ bk,
    const float* __restrict__ bv, const float* __restrict__ beta)
{
    extern __shared__ __align__(1024) char smem[];
    const uint32_t sbase = smem_u32(smem);
    const int tid  = threadIdx.x;
    const int lane = tid & 31;
    const int wid  = tid >> 5;
    const int bn = blockIdx.x;           // 0..11
    const int bm = blockIdx.y;           // 0..31
    const int sel = bn >> 2;             // 0=Q,1=K,2=V
    const int nck = (sel == 2) ? 8 : NCHUNK;

    const __half* __restrict__ Xb = g_Xc + (size_t)(bm * 128) * KSX;
    const __half* __restrict__ Wb = g_Wc + (size_t)(bn * 128) * KSW;

    const int r0  = tid >> 3;
    const int c16 = tid & 7;
    uint32_t so[4];
    #pragma unroll
    for (int j = 0; j < 4; j++)
        so[j] = swz((uint32_t)((r0 + 32 * j) * 128 + c16 * 16));

    const int wm = wid & 3;
    const int wn = wid >> 2;
    const int g  = lane >> 2;
    const int t  = lane & 3;

    const int a_row = wm * 32 + (lane & 15);
    const int a_kb  = (lane >> 4) * 16;
    const int b_row = wn * 64 + (lane & 7) + (lane >> 4) * 8;
    const int b_kb  = ((lane >> 3) & 1) * 16;

    float acc[2][8][4];
    #pragma unroll
    for (int i = 0; i < 2; i++)
        #pragma unroll
        for (int j = 0; j < 8; j++)
            #pragma unroll
            for (int q = 0; q < 4; q++) acc[i][j][q] = 0.f;

    #pragma unroll
    for (int s = 0; s < STAGES - 1; s++) {      // chunks 0,1: ac=bc=s
        uint32_t sA = sbase + s * STAGE_BYTES;
        uint32_t sB = sA + ATILE;
        const __half* gA = Xb + (size_t)s * KC + c16 * 8;
        const __half* gB = Wb + (size_t)s * KC + c16 * 8;
        #pragma unroll
        for (int j = 0; j < 4; j++) {
            cp16(sA + so[j], gA + (size_t)(r0 + 32 * j) * KSX);
            cp16(sB + so[j], gB + (size_t)(r0 + 32 * j) * KSW);
        }
        CP_COMMIT();
    }

    for (int i = 0; i < nck; i++) {
        CP_WAIT(STAGES - 2);
        __syncthreads();

        const int nxt = i + STAGES - 1;
        if (nxt < nck) {
            const int ac = nxt;
            const int bc = nxt & 7;
            const int st = nxt % STAGES;
            uint32_t sA = sbase + st * STAGE_BYTES;
            uint32_t sB = sA + ATILE;
            const __half* gA = Xb + (size_t)ac * KC + c16 * 8;
            const __half* gB = Wb + (size_t)bc * KC + c16 * 8;
            #pragma unroll
            for (int j = 0; j < 4; j++) {
                cp16(sA + so[j], gA + (size_t)(r0 + 32 * j) * KSX);
                cp16(sB + so[j], gB + (size_t)(r0 + 32 * j) * KSW);
            }
        }
        CP_COMMIT();

        const uint32_t sA = sbase + (i % STAGES) * STAGE_BYTES;
        const uint32_t sB = sA + ATILE;
        #pragma unroll
        for (int k16 = 0; k16 < 4; k16++) {
            uint32_t af[2][4];
            #pragma unroll
            for (int mt = 0; mt < 2; mt++) {
                uint32_t addr = sA + swz((uint32_t)((a_row + mt * 16) * 128
                                                    + k16 * 32 + a_kb));
                ldmx4(af[mt][0], af[mt][1], af[mt][2], af[mt][3], addr);
            }
            uint32_t bf[8][2];
            #pragma unroll
            for (int nt2 = 0; nt2 < 4; nt2++) {
                uint32_t addr = sB + swz((uint32_t)((b_row + nt2 * 16) * 128
                                                    + k16 * 32 + b_kb));
                uint32_t q0, q1, q2, q3;
                ldmx4(q0, q1, q2, q3, addr);
                bf[nt2 * 2 + 0][0] = q0; bf[nt2 * 2 + 0][1] = q1;
                bf[nt2 * 2 + 1][0] = q2; bf[nt2 * 2 + 1][1] = q3;
            }
            #pragma unroll
            for (int mt = 0; mt < 2; mt++)
                #pragma unroll
                for (int nt = 0; nt < 8; nt++)
                    mma16816(acc[mt][nt], af[mt], bf[nt][0], bf[nt][1]);
        }
    }

    const int nbase = (bn & 3) * 128;
    const float* __restrict__ bia = (sel == 0) ? bq : (sel == 1) ? bk : bv;
    float* __restrict__ dst = (sel == 0) ? g_Q : (sel == 1) ? g_K : g_V;
    const int head = (nbase + wn * 64) >> 6;
    const float scale = (sel == 0) ? (1.0f / (8.0f * expf(beta[head]))) : 1.0f;

    #pragma unroll
    for (int mt = 0; mt < 2; mt++) {
        const int m0 = bm * 128 + wm * 32 + mt * 16 + g;
        #pragma unroll
        for (int nt = 0; nt < 8; nt++) {
            const int nm   = nbase + wn * 64 + nt * 8 + t * 2;
            const int dcol = nm & 63;
            const float b0v = bia[nm], b1v = bia[nm + 1];
            #pragma unroll
            for (int half = 0; half < 2; half++) {
                const int m = m0 + half * 8;
                const int s_idx = m >> 1;
                const int b_idx = m & 1;
                float2 o;
                o.x = (acc[mt][nt][half * 2 + 0] + b0v) * scale;
                o.y = (acc[mt][nt][half * 2 + 1] + b1v) * scale;
                *(float2*)&dst[((size_t)(b_idx * NHEADS + head) * S_LEN + s_idx)
                               * DHEAD + dcol] = o;
            }
        }
    }
}

// ---------------------------------------------------------------------------
// Kernel C: dilation pass 0 reduction; last block per z combines partials
// AND computes the 32 window coefficients c[z][*] (sink softmax).
// ---------------------------------------------------------------------------
__global__ __launch_bounds__(256) void reduce_kv()
{
    const int z = blockIdx.x;
    const int c = blockIdx.y;
    const int t = threadIdx.x;
    const int squad = t >> 2;
    const int dpart = (t & 3) * 16;

    if (t == 0 && c == 0) g_done = 0;    // reset before coef_out launch

    const float* __restrict__ Q = g_Q + (size_t)z * S_LEN * DHEAD + dpart;
    const float* __restrict__ K = g_K + (size_t)z * S_LEN * DHEAD + dpart;
    const float* __restrict__ V = g_V + (size_t)z * S_LEN * DHEAD + dpart;

    float4 k2[4] = {}, v2[4] = {};
    const int s0 = c * 128;

    #pragma unroll
    for (int it = 0; it < 2; it++) {
        const size_t base = (size_t)(s0 + it * 64 + squad) * DHEAD;
        float4 q4[4], k4[4], v4[4];
        #pragma unroll
        for (int j = 0; j < 4; j++) {
            q4[j] = *(const float4*)(Q + base + j * 4);
            k4[j] = *(const float4*)(K + base + j * 4);
            v4[j] = *(const float4*)(V + base + j * 4);
        }
        float dot = 0.f;
        #pragma unroll
        for (int j = 0; j < 4; j++) {
            dot = fmaf(q4[j].x, k4[j].x, dot);
            dot = fmaf(q4[j].y, k4[j].y, dot);
            dot = fmaf(q4[j].z, k4[j].z, dot);
            dot = fmaf(q4[j].w, k4[j].w, dot);
        }
        dot += __shfl_xor_sync(0xFFFFFFFFu, dot, 1);
        dot += __shfl_xor_sync(0xFFFFFFFFu, dot, 2);
        const float w = 1.0f / (1.0f + expf(-dot));
        #pragma unroll
        for (int j = 0; j < 4; j++) {
            k2[j].x = fmaf(w, k4[j].x, k2[j].x);
            k2[j].y = fmaf(w, k4[j].y, k2[j].y);
            k2[j].z = fmaf(w, k4[j].z, k2[j].z);
            k2[j].w = fmaf(w, k4[j].w, k2[j].w);
            v2[j].x = fmaf(w, v4[j].x, v2[j].x);
            v2[j].y = fmaf(w, v4[j].y, v2[j].y);
            v2[j].z = fmaf(w, v4[j].z, v2[j].z);
            v2[j].w = fmaf(w, v4[j].w, v2[j].w);
        }
    }

    __shared__ __align__(16) float sk[64][64];
    __shared__ __align__(16) float sv[64][64];
    #pragma unroll
    for (int j = 0; j < 4; j++) {
        *(float4*)&sk[squad][dpart + j * 4] = k2[j];
        *(float4*)&sv[squad][dpart + j * 4] = v2[j];
    }
    __syncthreads();

    if (t < 128) {
        const int d = t & 63;
        float acc = 0.f;
        if (t < 64) {
            #pragma unroll 8
            for (int sq = 0; sq < 64; sq++) acc += sk[sq][d];
            g_k2p[(z * RCHUNK + c) * DHEAD + d] = acc;
        } else {
            #pragma unroll 8
            for (int sq = 0; sq < 64; sq++) acc += sv[sq][d];
            g_v2p[(z * RCHUNK + c) * DHEAD + d] = acc;
        }
    }
    __syncthreads();

    // Last block per z: combine partials, then compute c[z][*].
    __shared__ int s_last;
    __shared__ __align__(16) float s_k2f[DHEAD];
    __shared__ __align__(16) float s_scr[NWIN];
    if (t == 0) {
        __threadfence();
        const int old = atomicAdd(&g_cnt[z], 1);
        s_last = ((old & (RCHUNK - 1)) == (RCHUNK - 1)) ? 1 : 0;
        if (s_last) __threadfence();
    }
    __syncthreads();
    if (s_last) {
        if (t < 128) {
            const int d = t & 63;
            float acc = 0.f;
            if (t < 64) {
                #pragma unroll
                for (int cc = 0; cc < RCHUNK; cc++)
                    acc += g_k2p[(z * RCHUNK + cc) * DHEAD + d];
                g_k2[z * DHEAD + d] = acc;
                s_k2f[d] = acc;
            } else {
                #pragma unroll
                for (int cc = 0; cc < RCHUNK; cc++)
                    acc += g_v2p[(z * RCHUNK + cc) * DHEAD + d];
                g_v2[z * DHEAD + d] = acc;
            }
        }
        __syncthreads();

        {   // scores: w = t>>3 (0..31), part = t&7 handles 8 dims
            const int w = t >> 3, part = t & 7;
            const float* __restrict__ q =
                g_Q + ((size_t)z * S_LEN + (64 * w + 63)) * DHEAD + part * 8;
            const float4 q0 = *(const float4*)q;
            const float4 q1 = *(const float4*)(q + 4);
            const float4 k0 = *(const float4*)&s_k2f[part * 8];
            const float4 k1 = *(const float4*)&s_k2f[part * 8 + 4];
            float s = q0.x * k0.x + q0.y * k0.y + q0.z * k0.z + q0.w * k0.w
                    + q1.x * k1.x + q1.y * k1.y + q1.z * k1.z + q1.w * k1.w;
            s += __shfl_xor_sync(0xFFFFFFFFu, s, 1);
            s += __shfl_xor_sync(0xFFFFFFFFu, s, 2);
            s += __shfl_xor_sync(0xFFFFFFFFu, s, 4);
            if (part == 0) s_scr[w] = s;
        }
        __syncthreads();

        if (t < 32) {
            float s = s_scr[t];
            float mx = s;
            #pragma unroll
            for (int off = 16; off; off >>= 1)
                mx = fmaxf(mx, __shfl_xor_sync(0xFFFFFFFFu, mx, off));
            mx = fmaxf(mx, 0.f);
            const float e = expf(s - mx);
            float sum = e;
            #pragma unroll
            for (int off = 16; off; off >>= 1)
                sum += __shfl_xor_sync(0xFFFFFFFFu, sum, off);
            sum += expf(-mx);
            float cc = e / sum;
            if (t == 31) cc += 1.0f;
            g_c[z * NWIN + t] = cc;
        }
    }
}

// ---------------------------------------------------------------------------
// Kernel D: coef_out —
//   blocks [0,256):    P[z][n] = v2[z] . Wo[n, h*64 : h*64+64]; signal g_done.
//   blocks [256,320):  spin until g_done==256, then write one output row:
//                      out[2016+w, b, n] = bo[n] + sum_h c[z][w]*P[z][n].
// ---------------------------------------------------------------------------
__global__ __launch_bounds__(256) void coef_out(
    const float* __restrict__ Wo,
    float* __restrict__ out, const float* __restrict__ bo)
{
    const int tid = threadIdx.x;

    if (blockIdx.x < 256) {
        const int z  = blockIdx.x >> 4;
        const int nc = blockIdx.x & 15;
        const int h  = z & 7;

        __shared__ __align__(16) float s_v2[DHEAD];
        if (tid < DHEAD) s_v2[tid] = g_v2[z * DHEAD + tid];
        __syncthreads();

        const int warp = tid >> 5;
        const int lane = tid & 31;
        const float2 v2l = *(const float2*)&s_v2[lane * 2];

        #pragma unroll
        for (int j = 0; j < 4; j++) {
            const int n = nc * 32 + warp * 4 + j;
            const float2 wv = *(const float2*)(Wo + (size_t)n * DMODEL
                                               + h * DHEAD + lane * 2);
            float dot = v2l.x * wv.x + v2l.y * wv.y;
            #pragma unroll
            for (int off = 16; off; off >>= 1)
                dot += __shfl_xor_sync(0xFFFFFFFFu, dot, off);
            if (lane == 0) g_P[z * DMODEL + n] = dot;
        }
        __syncthreads();
        if (tid == 0) { __threadfence(); atomicAdd(&g_done, 1); }
        return;
    }

    // ---- out-row blocks ----------------------------------------------------
    const int idx   = blockIdx.x - 256;   // 0..63
    const int wb    = idx >> 1;
    const int batch = idx & 1;

    if (tid == 0) {
        while (atomicAdd(&g_done, 0) < 256) __nanosleep(64);
        __threadfence();
    }
    __syncthreads();

    __shared__ __align__(16) float s_c[NHEADS];
    if (tid < NHEADS)
        s_c[tid] = g_c[(batch * NHEADS + tid) * NWIN + wb];
    __syncthreads();

    const size_t orow = ((size_t)((2016 + wb) * BSZ + batch)) * DMODEL;
    #pragma unroll
    for (int j = 0; j < 2; j++) {
        const int n = j * 256 + tid;
        float acc = bo[n];
        #pragma unroll
        for (int h = 0; h < NHEADS; h++)
            acc = fmaf(s_c[h], g_P[(batch * NHEADS + h) * DMODEL + n], acc);
        out[orow + n] = acc;
    }
}

// ---------------------------------------------------------------------------
extern "C" void kernel_launch(void* const* d_in, const int* in_sizes, int n_in,
                              void* d_out, int out_size)
{
    const float* x    = (const float*)d_in[0];
    const float* Wq   = (const float*)d_in[1];
    const float* bq   = (const float*)d_in[2];
    const float* Wk   = (const float*)d_in[3];
    const float* bk   = (const float*)d_in[4];
    const float* Wv   = (const float*)d_in[5];
    const float* bv   = (const float*)d_in[6];
    const float* Wo   = (const float*)d_in[7];
    const float* bo   = (const float*)d_in[8];
    const float* beta = (const float*)d_in[9];
    float* out = (float*)d_out;

    cudaFuncSetAttribute(gemm_mma, cudaFuncAttributeMaxDynamicSharedMemorySize,
                         SMEM_BYTES);

    convert_xw<<<CONV_BLOCKS + FILL_BLOCKS, 256>>>(x, Wq, Wk, Wv, out, bo);
    gemm_mma<<<dim3(NTOT / 128, MROWS / 128), 256, SMEM_BYTES>>>(bq, bk, bv, beta);
    reduce_kv<<<dim3(ZB, RCHUNK), 256>>>();
    coef_out<<<320, 256>>>(Wo, out, bo);
}

// round 11
// speedup vs baseline: 5.9246x; 1.0011x over previous
#include <cuda_runtime.h>
#include <cuda_fp16.h>
#include <math.h>
#include <stdint.h>

#define S_LEN  2048
#define BSZ    2
#define DMODEL 512
#define NHEADS 8
#define DHEAD  64
#define ZB     (BSZ*NHEADS)          // 16
#define MROWS  (S_LEN*BSZ)           // 4096
#define NWIN   32
#define KSX    1024                  // X row: [hi(512) | lo(512)] fp16
#define KSW    512                   // W row: hi only, fp16
#define NTOT   1536                  // Q,K,V columns stacked
#define KC     64                    // K chunk (fp16) = 128B rows
#define NCHUNK 16                    // Q,K: hi(8)+lo(8);  V: hi(8) only
#define STAGES 3
#define ATILE  16384                 // 128 x 64 fp16
#define BTILE  16384
#define STAGE_BYTES (ATILE+BTILE)
#define SMEM_BYTES  (STAGES*STAGE_BYTES)   // 96 KB
#define RCHUNK 16                    // s-chunks per z in reduce_kv

// Kernel-1 block roles
#define XCV_BLOCKS  512              // X convert: 4 float4 / thread
#define WCV_BLOCKS  768              // W convert: 1 float4 / thread
#define FIL_BLOCKS  512              // bias fill of ALL 2048 rows
#define K1_BLOCKS   (XCV_BLOCKS + WCV_BLOCKS + FIL_BLOCKS)   // 1792

// ---------------- static scratch (no cudaMalloc allowed) -------------------
__device__ __align__(16) __half g_Xc[(size_t)MROWS*KSX];  // 8.4 MB
__device__ __align__(16) __half g_Wc[(size_t)NTOT*KSW];   // 1.6 MB
__device__ __align__(16) float g_Q[(size_t)ZB*S_LEN*DHEAD];
__device__ __align__(16) float g_K[(size_t)ZB*S_LEN*DHEAD];
__device__ __align__(16) float g_V[(size_t)ZB*S_LEN*DHEAD];
__device__ __align__(16) float g_k2p[ZB*RCHUNK*DHEAD];
__device__ __align__(16) float g_v2p[ZB*RCHUNK*DHEAD];
__device__ __align__(16) float g_k2[ZB*DHEAD];
__device__ __align__(16) float g_v2[ZB*DHEAD];
__device__ int   g_cnt[ZB];          // replay-safe via &15
__device__ __align__(16) float g_c[ZB*NWIN];

// ---------------- helpers ---------------------------------------------------
__device__ __forceinline__ uint32_t smem_u32(const void* p) {
    uint32_t a;
    asm("{ .reg .u64 t; cvta.to.shared.u64 t, %1; cvt.u32.u64 %0, t; }"
        : "=r"(a) : "l"(p));
    return a;
}
__device__ __forceinline__ uint32_t swz(uint32_t off) {
    return off ^ ((off >> 3) & 0x70);      // SW128
}
__device__ __forceinline__ void cp16(uint32_t saddr, const void* g) {
    asm volatile("cp.async.cg.shared.global [%0], [%1], 16;"
                 :: "r"(saddr), "l"(g) : "memory");
}
#define CP_COMMIT() asm volatile("cp.async.commit_group;" ::: "memory")
#define CP_WAIT(n)  asm volatile("cp.async.wait_group %0;" :: "n"(n) : "memory")

__device__ __forceinline__ void ldmx4(uint32_t& r0, uint32_t& r1,
                                      uint32_t& r2, uint32_t& r3, uint32_t a) {
    asm volatile("ldmatrix.sync.aligned.m8n8.x4.shared.b16 {%0,%1,%2,%3}, [%4];"
                 : "=r"(r0), "=r"(r1), "=r"(r2), "=r"(r3) : "r"(a));
}
__device__ __forceinline__ void mma16816(float* c, const uint32_t* a,
                                         uint32_t b0, uint32_t b1) {
    asm volatile(
        "mma.sync.aligned.m16n8k16.row.col.f32.f16.f16.f32 "
        "{%0,%1,%2,%3}, {%4,%5,%6,%7}, {%8,%9}, {%0,%1,%2,%3};"
        : "+f"(c[0]), "+f"(c[1]), "+f"(c[2]), "+f"(c[3])
        : "r"(a[0]), "r"(a[1]), "r"(a[2]), "r"(a[3]), "r"(b0), "r"(b1));
}

// ---------------------------------------------------------------------------
// Kernel A:
//   blocks [0,512)        : X fp16 split [hi|lo], 4 float4/thread
//   blocks [512,1280)     : W -> fp16 hi
//   blocks [1280,1792)    : bias fill of ALL 2048 output rows (atomic base)
// ---------------------------------------------------------------------------
__global__ __launch_bounds__(256) void convert_xw(
    const float* __restrict__ x,
    const float* __restrict__ Wq, const float* __restrict__ Wk,
    const float* __restrict__ Wv,
    float* __restrict__ out, const float* __restrict__ bo)
{
    const int tid = threadIdx.x;
    const int bid = blockIdx.x;
    const int W4PM = DMODEL / 4;                       // 128 float4 per row

    if (bid < XCV_BLOCKS) {
        #pragma unroll
        for (int j = 0; j < 4; j++) {
            const int tid4 = bid * 1024 + j * 256 + tid;
            const float4 v = ((const float4*)x)[tid4];
            const int m    = tid4 / W4PM;
            const int koff = (tid4 % W4PM) * 4;
            const size_t dbase = (size_t)m * KSX;

            __half2 hi01 = __halves2half2(__float2half_rn(v.x), __float2half_rn(v.y));
            __half2 hi23 = __halves2half2(__float2half_rn(v.z), __float2half_rn(v.w));
            __half2 lo01 = __halves2half2(
                __float2half_rn(v.x - __half2float(__low2half(hi01))),
                __float2half_rn(v.y - __half2float(__high2half(hi01))));
            __half2 lo23 = __halves2half2(
                __float2half_rn(v.z - __half2float(__low2half(hi23))),
                __float2half_rn(v.w - __half2float(__high2half(hi23))));

            __half2* d0 = (__half2*)(g_Xc + dbase + koff);
            __half2* d1 = (__half2*)(g_Xc + dbase + 512 + koff);
            d0[0] = hi01; d0[1] = hi23;
            d1[0] = lo01; d1[1] = lo23;
        }
    } else if (bid < XCV_BLOCKS + WCV_BLOCKS) {
        const int wi   = (bid - XCV_BLOCKS) * 256 + tid;
        const int n    = wi / W4PM;
        const int koff = (wi % W4PM) * 4;
        const int sel  = n >> 9, row = n & 511;
        const float* W = (sel == 0) ? Wq : (sel == 1) ? Wk : Wv;
        const float4 v = *(const float4*)(W + (size_t)row * DMODEL + koff);

        __half2 hi01 = __halves2half2(__float2half_rn(v.x), __float2half_rn(v.y));
        __half2 hi23 = __halves2half2(__float2half_rn(v.z), __float2half_rn(v.w));
        __half2* d0 = (__half2*)(g_Wc + (size_t)n * KSW + koff);
        d0[0] = hi01; d0[1] = hi23;
    } else {
        __shared__ __align__(16) float4 sb[128];
        if (tid < 128) sb[tid] = ((const float4*)bo)[tid];
        __syncthreads();
        const int blk = bid - (XCV_BLOCKS + WCV_BLOCKS);   // 0..511
        float4* out4 = (float4*)out;
        #pragma unroll
        for (int j = 0; j < 4; j++) {
            const int idx = blk * 1024 + j * 256 + tid;
            out4[idx] = sb[idx & 127];
        }
    }
}

// ---------------------------------------------------------------------------
// Kernel B: fp16 warp-MMA GEMM.  Q,K blocks: 16 chunks (Xhi+Xlo)@Whi.
// V blocks (sel==2): 8 chunks (Xhi only) — V error is strictly linear.
// ---------------------------------------------------------------------------
__global__ __launch_bounds__(256, 2) void gemm_mma(
    const float* __restrict__ bq, const float* __restrict__ bk,
    const float* __restrict__ bv, const float* __restrict__ beta)
{
    extern __shared__ __align__(1024) char smem[];
    const uint32_t sbase = smem_u32(smem);
    const int tid  = threadIdx.x;
    const int lane = tid & 31;
    const int wid  = tid >> 5;
    const int bn = blockIdx.x;           // 0..11
    const int bm = blockIdx.y;           // 0..31
    const int sel = bn >> 2;             // 0=Q,1=K,2=V
    const int nck = (sel == 2) ? 8 : NCHUNK;

    const __half* __restrict__ Xb = g_Xc + (size_t)(bm * 128) * KSX;
    const __half* __restrict__ Wb = g_Wc + (size_t)(bn * 128) * KSW;

    const int r0  = tid >> 3;
    const int c16 = tid & 7;
    uint32_t so[4];
    #pragma unroll
    for (int j = 0; j < 4; j++)
        so[j] = swz((uint32_t)((r0 + 32 * j) * 128 + c16 * 16));

    const int wm = wid & 3;
    const int wn = wid >> 2;
    const int g  = lane >> 2;
    const int t  = lane & 3;

    const int a_row = wm * 32 + (lane & 15);
    const int a_kb  = (lane >> 4) * 16;
    const int b_row = wn * 64 + (lane & 7) + (lane >> 4) * 8;
    const int b_kb  = ((lane >> 3) & 1) * 16;

    float acc[2][8][4];
    #pragma unroll
    for (int i = 0; i < 2; i++)
        #pragma unroll
        for (int j = 0; j < 8; j++)
            #pragma unroll
            for (int q = 0; q < 4; q++) acc[i][j][q] = 0.f;

    #pragma unroll
    for (int s = 0; s < STAGES - 1; s++) {      // chunks 0,1: ac=bc=s
        uint32_t sA = sbase + s * STAGE_BYTES;
        uint32_t sB = sA + ATILE;
        const __half* gA = Xb + (size_t)s * KC + c16 * 8;
        const __half* gB = Wb + (size_t)s * KC + c16 * 8;
        #pragma unroll
        for (int j = 0; j < 4; j++) {
            cp16(sA + so[j], gA + (size_t)(r0 + 32 * j) * KSX);
            cp16(sB + so[j], gB + (size_t)(r0 + 32 * j) * KSW);
        }
        CP_COMMIT();
    }

    for (int i = 0; i < nck; i++) {
        CP_WAIT(STAGES - 2);
        __syncthreads();

        const int nxt = i + STAGES - 1;
        if (nxt < nck) {
            const int ac = nxt;
            const int bc = nxt & 7;
            const int st = nxt % STAGES;
            uint32_t sA = sbase + st * STAGE_BYTES;
            uint32_t sB = sA + ATILE;
            const __half* gA = Xb + (size_t)ac * KC + c16 * 8;
            const __half* gB = Wb + (size_t)bc * KC + c16 * 8;
            #pragma unroll
            for (int j = 0; j < 4; j++) {
                cp16(sA + so[j], gA + (size_t)(r0 + 32 * j) * KSX);
                cp16(sB + so[j], gB + (size_t)(r0 + 32 * j) * KSW);
            }
        }
        CP_COMMIT();

        const uint32_t sA = sbase + (i % STAGES) * STAGE_BYTES;
        const uint32_t sB = sA + ATILE;
        #pragma unroll
        for (int k16 = 0; k16 < 4; k16++) {
            uint32_t af[2][4];
            #pragma unroll
            for (int mt = 0; mt < 2; mt++) {
                uint32_t addr = sA + swz((uint32_t)((a_row + mt * 16) * 128
                                                    + k16 * 32 + a_kb));
                ldmx4(af[mt][0], af[mt][1], af[mt][2], af[mt][3], addr);
            }
            uint32_t bf[8][2];
            #pragma unroll
            for (int nt2 = 0; nt2 < 4; nt2++) {
                uint32_t addr = sB + swz((uint32_t)((b_row + nt2 * 16) * 128
                                                    + k16 * 32 + b_kb));
                uint32_t q0, q1, q2, q3;
                ldmx4(q0, q1, q2, q3, addr);
                bf[nt2 * 2 + 0][0] = q0; bf[nt2 * 2 + 0][1] = q1;
                bf[nt2 * 2 + 1][0] = q2; bf[nt2 * 2 + 1][1] = q3;
            }
            #pragma unroll
            for (int mt = 0; mt < 2; mt++)
                #pragma unroll
                for (int nt = 0; nt < 8; nt++)
                    mma16816(acc[mt][nt], af[mt], bf[nt][0], bf[nt][1]);
        }
    }

    const int nbase = (bn & 3) * 128;
    const float* __restrict__ bia = (sel == 0) ? bq : (sel == 1) ? bk : bv;
    float* __restrict__ dst = (sel == 0) ? g_Q : (sel == 1) ? g_K : g_V;
    const int head = (nbase + wn * 64) >> 6;
    const float scale = (sel == 0) ? (1.0f / (8.0f * expf(beta[head]))) : 1.0f;

    #pragma unroll
    for (int mt = 0; mt < 2; mt++) {
        const int m0 = bm * 128 + wm * 32 + mt * 16 + g;
        #pragma unroll
        for (int nt = 0; nt < 8; nt++) {
            const int nm   = nbase + wn * 64 + nt * 8 + t * 2;
            const int dcol = nm & 63;
            const float b0v = bia[nm], b1v = bia[nm + 1];
            #pragma unroll
            for (int half = 0; half < 2; half++) {
                const int m = m0 + half * 8;
                const int s_idx = m >> 1;
                const int b_idx = m & 1;
                float2 o;
                o.x = (acc[mt][nt][half * 2 + 0] + b0v) * scale;
                o.y = (acc[mt][nt][half * 2 + 1] + b1v) * scale;
                *(float2*)&dst[((size_t)(b_idx * NHEADS + head) * S_LEN + s_idx)
                               * DHEAD + dcol] = o;
            }
        }
    }
}

// ---------------------------------------------------------------------------
// Kernel C: dilation pass 0 reduction; last block per z combines partials
// AND computes the 32 window coefficients c[z][*] (sink softmax).
// ---------------------------------------------------------------------------
__global__ __launch_bounds__(256) void reduce_kv()
{
    const int z = blockIdx.x;
    const int c = blockIdx.y;
    const int t = threadIdx.x;
    const int squad = t >> 2;
    const int dpart = (t & 3) * 16;

    const float* __restrict__ Q = g_Q + (size_t)z * S_LEN * DHEAD + dpart;
    const float* __restrict__ K = g_K + (size_t)z * S_LEN * DHEAD + dpart;
    const float* __restrict__ V = g_V + (size_t)z * S_LEN * DHEAD + dpart;

    float4 k2[4] = {}, v2[4] = {};
    const int s0 = c * 128;

    #pragma unroll
    for (int it = 0; it < 2; it++) {
        const size_t base = (size_t)(s0 + it * 64 + squad) * DHEAD;
        float4 q4[4], k4[4], v4[4];
        #pragma unroll
        for (int j = 0; j < 4; j++) {
            q4[j] = *(const float4*)(Q + base + j * 4);
            k4[j] = *(const float4*)(K + base + j * 4);
            v4[j] = *(const float4*)(V + base + j * 4);
        }
        float dot = 0.f;
        #pragma unroll
        for (int j = 0; j < 4; j++) {
            dot = fmaf(q4[j].x, k4[j].x, dot);
            dot = fmaf(q4[j].y, k4[j].y, dot);
            dot = fmaf(q4[j].z, k4[j].z, dot);
            dot = fmaf(q4[j].w, k4[j].w, dot);
        }
        dot += __shfl_xor_sync(0xFFFFFFFFu, dot, 1);
        dot += __shfl_xor_sync(0xFFFFFFFFu, dot, 2);
        const float w = 1.0f / (1.0f + expf(-dot));
        #pragma unroll
        for (int j = 0; j < 4; j++) {
            k2[j].x = fmaf(w, k4[j].x, k2[j].x);
            k2[j].y = fmaf(w, k4[j].y, k2[j].y);
            k2[j].z = fmaf(w, k4[j].z, k2[j].z);
            k2[j].w = fmaf(w, k4[j].w, k2[j].w);
            v2[j].x = fmaf(w, v4[j].x, v2[j].x);
            v2[j].y = fmaf(w, v4[j].y, v2[j].y);
            v2[j].z = fmaf(w, v4[j].z, v2[j].z);
            v2[j].w = fmaf(w, v4[j].w, v2[j].w);
        }
    }

    __shared__ __align__(16) float sk[64][64];
    __shared__ __align__(16) float sv[64][64];
    #pragma unroll
    for (int j = 0; j < 4; j++) {
        *(float4*)&sk[squad][dpart + j * 4] = k2[j];
        *(float4*)&sv[squad][dpart + j * 4] = v2[j];
    }
    __syncthreads();

    if (t < 128) {
        const int d = t & 63;
        float acc = 0.f;
        if (t < 64) {
            #pragma unroll 8
            for (int sq = 0; sq < 64; sq++) acc += sk[sq][d];
            g_k2p[(z * RCHUNK + c) * DHEAD + d] = acc;
        } else {
            #pragma unroll 8
            for (int sq = 0; sq < 64; sq++) acc += sv[sq][d];
            g_v2p[(z * RCHUNK + c) * DHEAD + d] = acc;
        }
    }
    __syncthreads();

    // Last block per z: combine partials, then compute c[z][*].
    __shared__ int s_last;
    __shared__ __align__(16) float s_k2f[DHEAD];
    __shared__ __align__(16) float s_scr[NWIN];
    if (t == 0) {
        __threadfence();
        const int old = atomicAdd(&g_cnt[z], 1);
        s_last = ((old & (RCHUNK - 1)) == (RCHUNK - 1)) ? 1 : 0;
        if (s_last) __threadfence();
    }
    __syncthreads();
    if (s_last) {
        if (t < 128) {
            const int d = t & 63;
            float acc = 0.f;
            if (t < 64) {
                #pragma unroll
                for (int cc = 0; cc < RCHUNK; cc++)
                    acc += g_k2p[(z * RCHUNK + cc) * DHEAD + d];
                g_k2[z * DHEAD + d] = acc;
                s_k2f[d] = acc;
            } else {
                #pragma unroll
                for (int cc = 0; cc < RCHUNK; cc++)
                    acc += g_v2p[(z * RCHUNK + cc) * DHEAD + d];
                g_v2[z * DHEAD + d] = acc;
            }
        }
        __syncthreads();

        {   // scores: w = t>>3 (0..31), part = t&7 handles 8 dims
            const int w = t >> 3, part = t & 7;
            const float* __restrict__ q =
                g_Q + ((size_t)z * S_LEN + (64 * w + 63)) * DHEAD + part * 8;
            const float4 q0 = *(const float4*)q;
            const float4 q1 = *(const float4*)(q + 4);
            const float4 k0 = *(const float4*)&s_k2f[part * 8];
            const float4 k1 = *(const float4*)&s_k2f[part * 8 + 4];
            float s = q0.x * k0.x + q0.y * k0.y + q0.z * k0.z + q0.w * k0.w
                    + q1.x * k1.x + q1.y * k1.y + q1.z * k1.z + q1.w * k1.w;
            s += __shfl_xor_sync(0xFFFFFFFFu, s, 1);
            s += __shfl_xor_sync(0xFFFFFFFFu, s, 2);
            s += __shfl_xor_sync(0xFFFFFFFFu, s, 4);
            if (part == 0) s_scr[w] = s;
        }
        __syncthreads();

        if (t < 32) {
            float s = s_scr[t];
            float mx = s;
            #pragma unroll
            for (int off = 16; off; off >>= 1)
                mx = fmaxf(mx, __shfl_xor_sync(0xFFFFFFFFu, mx, off));
            mx = fmaxf(mx, 0.f);
            const float e = expf(s - mx);
            float sum = e;
            #pragma unroll
            for (int off = 16; off; off >>= 1)
                sum += __shfl_xor_sync(0xFFFFFFFFu, sum, off);
            sum += expf(-mx);
            float cc = e / sum;
            if (t == 31) cc += 1.0f;
            g_c[z * NWIN + t] = cc;
        }
    }
}

// ---------------------------------------------------------------------------
// Kernel D: coef_atomic — 256 blocks, block (z, nc) covers n = nc*32..+31.
// dot = v2[z] . Wo[n, h*64:+64] (xor-reduce leaves sum in ALL lanes);
// lane w adds c[z][w]*dot into out[2016+w, batch, n] (bias pre-filled).
// ---------------------------------------------------------------------------
__global__ __launch_bounds__(256) void coef_atomic(
    const float* __restrict__ Wo, float* __restrict__ out)
{
    const int tid = threadIdx.x;
    const int z   = blockIdx.x >> 4;
    const int nc  = blockIdx.x & 15;
    const int h   = z & 7;
    const int batch = z >> 3;

    __shared__ __align__(16) float s_v2[DHEAD];
    __shared__ __align__(16) float s_c[NWIN];
    if (tid < DHEAD) s_v2[tid] = g_v2[z * DHEAD + tid];
    else if (tid < DHEAD + NWIN) s_c[tid - DHEAD] = g_c[z * NWIN + (tid - DHEAD)];
    __syncthreads();

    const int warp = tid >> 5;
    const int lane = tid & 31;
    const float2 v2l = *(const float2*)&s_v2[lane * 2];
    const float  cw  = s_c[lane];            // coefficient for window = lane

    #pragma unroll
    for (int j = 0; j < 4; j++) {
        const int n = nc * 32 + warp * 4 + j;
        const float2 wv = *(const float2*)(Wo + (size_t)n * DMODEL
                                           + h * DHEAD + lane * 2);
        float dot = v2l.x * wv.x + v2l.y * wv.y;
        #pragma unroll
        for (int off = 16; off; off >>= 1)
            dot += __shfl_xor_sync(0xFFFFFFFFu, dot, off);
        // all lanes hold the full dot; lane w handles window w
        atomicAdd(&out[((size_t)((2016 + lane) * BSZ + batch)) * DMODEL + n],
                  cw * dot);
    }
}

// ---------------------------------------------------------------------------
extern "C" void kernel_launch(void* const* d_in, const int* in_sizes, int n_in,
                              void* d_out, int out_size)
{
    const float* x    = (const float*)d_in[0];
    const float* Wq   = (const float*)d_in[1];
    const float* bq   = (const float*)d_in[2];
    const float* Wk   = (const float*)d_in[3];
    const float* bk   = (const float*)d_in[4];
    const float* Wv   = (const float*)d_in[5];
    const float* bv   = (const float*)d_in[6];
    const float* Wo   = (const float*)d_in[7];
    const float* bo   = (const float*)d_in[8];
    const float* beta = (const float*)d_in[9];
    float* out = (float*)d_out;

    cudaFuncSetAttribute(gemm_mma, cudaFuncAttributeMaxDynamicSharedMemorySize,
                         SMEM_BYTES);

    convert_xw<<<K1_BLOCKS, 256>>>(x, Wq, Wk, Wv, out, bo);
    gemm_mma<<<dim3(NTOT / 128, MROWS / 128), 256, SMEM_BYTES>>>(bq, bk, bv, beta);
    reduce_kv<<<dim3(ZB, RCHUNK), 256>>>();
    coef_atomic<<<256, 256>>>(Wo, out);
}